// round 3
// baseline (speedup 1.0000x reference)
#include <cuda_runtime.h>
#include <math.h>

// ---------------------------------------------------------------------------
// UNet forward (B=4, H=W=256), fp32 direct convolutions, graph-capturable.
// All intermediates in __device__ globals (no allocation anywhere).
// ---------------------------------------------------------------------------

#define B4 4

// ---------------- workspace buffers ----------------
__device__ float g_dyn [4*32*255*255];   // dyn conv + mish
__device__ float g_c1  [4*32*256*256];   // encoder skip 1
__device__ float g_p1  [4*32*128*128];
__device__ float g_t2  [4*128*128*128];
__device__ float g_c2  [4*128*128*128];  // skip 2
__device__ float g_p2  [4*128*64*64];
__device__ float g_t3  [4*256*64*64];
__device__ float g_c3  [4*256*64*64];    // skip 3
__device__ float g_p3  [4*256*32*32];
__device__ float g_t4  [4*512*32*32];
__device__ float g_h4  [4*512*32*32];
__device__ float g_cat3[4*768*64*64];
__device__ float g_u3t [4*256*64*64];
__device__ float g_u3  [4*256*64*64];
__device__ float g_cat2[4*384*128*128];
__device__ float g_u2t [4*128*128*128];
__device__ float g_u2  [4*128*128*128];
__device__ float g_cat1[4*160*256*256];
__device__ float g_u1t [4*32*256*256];
__device__ float g_u1  [4*32*256*256];
__device__ float g_bnscale[512];
__device__ float g_bnshift[512];

__device__ __forceinline__ float mishf(float x) {
    float sp = (x > 20.f) ? x : log1pf(expf(x));
    return x * tanhf(sp);
}

// ---------------- tiled direct conv (KxK, stride 1) ----------------
// Block: 256 threads (16x16), each thread computes a 2x2 output patch,
// block covers a 32x32 spatial tile for CO_BLK=8 output channels.
#define CO_BLK 8

template<int K, int PAD, bool ACT>
__global__ void conv_tiled_kernel(const float* __restrict__ in,
                                  const float* __restrict__ wt,
                                  const float* __restrict__ bias,
                                  float* __restrict__ out,
                                  int Ci, int Hi, int Wi,
                                  int Co, int Ho, int Wo, int tilesX)
{
    constexpr int TILE = 32;
    constexpr int S = TILE + K - 1;
    __shared__ float s_in[S * S];
    __shared__ float s_w[CO_BLK * K * K];

    int tileId = blockIdx.x;
    int tileY = tileId / tilesX;
    int tileX = tileId - tileY * tilesX;
    int cog = blockIdx.y;
    int b   = blockIdx.z;

    int x0 = tileX * TILE, y0 = tileY * TILE;
    int tid = threadIdx.x;
    int tx = tid & 15, ty = tid >> 4;

    const float* inB = in + (long)b * Ci * Hi * Wi;
    const float* wB  = wt + (long)cog * CO_BLK * Ci * K * K;

    float acc[CO_BLK][4];
#pragma unroll
    for (int co = 0; co < CO_BLK; co++) {
        acc[co][0] = acc[co][1] = acc[co][2] = acc[co][3] = 0.f;
    }

    for (int ci = 0; ci < Ci; ci++) {
        const float* inC = inB + (long)ci * Hi * Wi;
        for (int i = tid; i < S * S; i += 256) {
            int iy = i / S, ix = i - iy * S;
            int gy = y0 - PAD + iy, gx = x0 - PAD + ix;
            float v = 0.f;
            if (gy >= 0 && gy < Hi && gx >= 0 && gx < Wi) v = inC[gy * Wi + gx];
            s_in[i] = v;
        }
        if (tid < CO_BLK * K * K) {
            int co = tid / (K * K), t = tid - co * K * K;
            s_w[tid] = wB[(long)co * Ci * K * K + ci * K * K + t];
        }
        __syncthreads();

        float p[(K + 1) * (K + 1)];
        int bx = tx * 2, by = ty * 2;
#pragma unroll
        for (int r = 0; r < K + 1; r++)
#pragma unroll
            for (int c = 0; c < K + 1; c++)
                p[r * (K + 1) + c] = s_in[(by + r) * S + bx + c];

#pragma unroll
        for (int co = 0; co < CO_BLK; co++) {
#pragma unroll
            for (int r = 0; r < K; r++) {
#pragma unroll
                for (int c = 0; c < K; c++) {
                    float wv = s_w[co * K * K + r * K + c];
                    acc[co][0] = fmaf(p[ r      * (K + 1) + c    ], wv, acc[co][0]);
                    acc[co][1] = fmaf(p[ r      * (K + 1) + c + 1], wv, acc[co][1]);
                    acc[co][2] = fmaf(p[(r + 1) * (K + 1) + c    ], wv, acc[co][2]);
                    acc[co][3] = fmaf(p[(r + 1) * (K + 1) + c + 1], wv, acc[co][3]);
                }
            }
        }
        __syncthreads();
    }

#pragma unroll
    for (int co = 0; co < CO_BLK; co++) {
        int oc = cog * CO_BLK + co;
        float bi = bias[oc];
        float* outC = out + ((long)b * Co + oc) * Ho * Wo;
#pragma unroll
        for (int d = 0; d < 4; d++) {
            int oy = y0 + ty * 2 + (d >> 1);
            int ox = x0 + tx * 2 + (d & 1);
            if (oy < Ho && ox < Wo) {
                float v = acc[co][d] + bi;
                if (ACT) v = mishf(v);
                outC[oy * Wo + ox] = v;
            }
        }
    }
}

// ---------------- dynamic per-sample conv (K=4, pad=1) + mish ----------------
// x: (4,1,256,256), w: (4,32,4,4) -> out (4,32,255,255)
__global__ void dyn_conv_mish_kernel(const float* __restrict__ x,
                                     const float* __restrict__ w,
                                     float* __restrict__ out)
{
    const int Ho = 255, Wo = 255, Hi = 256, Wi = 256;
    int idx = blockIdx.x * blockDim.x + threadIdx.x;
    int total = 4 * 32 * Ho * Wo;
    if (idx >= total) return;
    int ox = idx % Wo;
    int t = idx / Wo;
    int oy = t % Ho; t /= Ho;
    int co = t % 32; int b = t / 32;
    const float* xb = x + b * Hi * Wi;
    const float* wb = w + (b * 32 + co) * 16;
    float acc = 0.f;
#pragma unroll
    for (int ky = 0; ky < 4; ky++) {
        int iy = oy - 1 + ky;
        if (iy < 0 || iy >= Hi) continue;
#pragma unroll
        for (int kx = 0; kx < 4; kx++) {
            int ix = ox - 1 + kx;
            if (ix < 0 || ix >= Wi) continue;
            acc = fmaf(xb[iy * Wi + ix], wb[ky * 4 + kx], acc);
        }
    }
    out[idx] = mishf(acc);
}

// ---------------- 2x2 maxpool ----------------
__global__ void maxpool_kernel(const float* __restrict__ in, float* __restrict__ out,
                               int C, int Hi, int Wi)
{
    int Ho = Hi >> 1, Wo = Wi >> 1;
    int idx = blockIdx.x * blockDim.x + threadIdx.x;
    int total = B4 * C * Ho * Wo;
    if (idx >= total) return;
    int ox = idx % Wo;
    int t = idx / Wo;
    int oy = t % Ho;
    int bc = t / Ho;
    const float* p = in + (long)bc * Hi * Wi + (oy * 2) * Wi + ox * 2;
    float v0 = p[0], v1 = p[1], v2 = p[Wi], v3 = p[Wi + 1];
    out[idx] = fmaxf(fmaxf(v0, v1), fmaxf(v2, v3));
}

// ---------------- batchnorm stats (per-channel over B,H,W) ----------------
// h: (4,512,32,32); one block per channel.
__global__ void bn_stats_kernel(const float* __restrict__ h,
                                const float* __restrict__ g,
                                const float* __restrict__ be,
                                float* __restrict__ scale,
                                float* __restrict__ shift)
{
    __shared__ float ss[256], ss2[256];
    int c = blockIdx.x;
    int tid = threadIdx.x;
    float s = 0.f, s2 = 0.f;
    for (int b = 0; b < 4; b++) {
        const float* p = h + ((long)b * 512 + c) * 1024;
        for (int i = tid; i < 1024; i += 256) {
            float v = p[i];
            s += v; s2 += v * v;
        }
    }
    ss[tid] = s; ss2[tid] = s2;
    __syncthreads();
    for (int off = 128; off > 0; off >>= 1) {
        if (tid < off) { ss[tid] += ss[tid + off]; ss2[tid] += ss2[tid + off]; }
        __syncthreads();
    }
    if (tid == 0) {
        float mean = ss[0] * (1.f / 4096.f);
        float var = ss2[0] * (1.f / 4096.f) - mean * mean;
        float sc = g[c] * rsqrtf(var + 1e-5f);
        scale[c] = sc;
        shift[c] = be[c] - mean * sc;
    }
}

// ---------------- bilinear x2 upsample (align_corners=True), optional BN affine,
// writing into a concat buffer at channel offset 0 with channel stride Ccat ----
__global__ void up2_kernel(const float* __restrict__ in, float* __restrict__ outbase,
                           int C, int H, int W, int Ccat,
                           const float* __restrict__ scale,
                           const float* __restrict__ shift)
{
    int Ho = 2 * H, Wo = 2 * W;
    long idx = (long)blockIdx.x * blockDim.x + threadIdx.x;
    long total = (long)B4 * C * Ho * Wo;
    if (idx >= total) return;
    int ox = idx % Wo;
    long t = idx / Wo;
    int oy = t % Ho; t /= Ho;
    int c = t % C; int b = (int)(t / C);

    float ry = (float)((double)(H - 1) / (double)(Ho - 1));
    float rx = (float)((double)(W - 1) / (double)(Wo - 1));
    float sy = (float)oy * ry;
    float sx = (float)ox * rx;
    int y0 = (int)floorf(sy);
    int x0 = (int)floorf(sx);
    float fy = sy - (float)y0;
    float fx = sx - (float)x0;
    int y1 = min(y0 + 1, H - 1);
    int x1 = min(x0 + 1, W - 1);

    const float* inC = in + ((long)b * C + c) * H * W;
    float a0 = inC[y0 * W + x0] * (1.f - fy) + inC[y1 * W + x0] * fy;
    float a1 = inC[y0 * W + x1] * (1.f - fy) + inC[y1 * W + x1] * fy;
    float v = a0 * (1.f - fx) + a1 * fx;
    if (scale) v = v * scale[c] + shift[c];
    outbase[((long)b * Ccat + c) * Ho * Wo + (long)oy * Wo + ox] = v;
}

// ---------------- concat copy: skip (B,C2,HW) -> cat[:, C1:C1+C2] ----------------
__global__ void concat_copy_kernel(const float* __restrict__ skip, float* __restrict__ cat,
                                   int C1, int C2, int HW)
{
    int Ccat = C1 + C2;
    long idx = (long)blockIdx.x * blockDim.x + threadIdx.x;
    long total = (long)B4 * C2 * HW;
    if (idx >= total) return;
    int hw = idx % HW;
    long t = idx / HW;
    int c = t % C2; int b = (int)(t / C2);
    cat[((long)b * Ccat + C1 + c) * HW + hw] = skip[((long)b * C2 + c) * HW + hw];
}

// ---------------- final 1x1 conv (32 -> 1) ----------------
__global__ void conv1x1_kernel(const float* __restrict__ in,
                               const float* __restrict__ w,
                               const float* __restrict__ bias,
                               float* __restrict__ out)
{
    int idx = blockIdx.x * blockDim.x + threadIdx.x;
    int total = 4 * 65536;
    if (idx >= total) return;
    int hw = idx & 65535;
    int b = idx >> 16;
    float acc = bias[0];
    const float* p = in + (long)b * 32 * 65536 + hw;
#pragma unroll
    for (int ci = 0; ci < 32; ci++) acc = fmaf(p[(long)ci * 65536], w[ci], acc);
    out[idx] = acc;
}

// ---------------------------------------------------------------------------
// Host side
// ---------------------------------------------------------------------------
static float* sym(const void* symbol) {
    void* p = nullptr;
    cudaGetSymbolAddress(&p, symbol);
    return (float*)p;
}

static void launch_conv3(const float* in, const float* wt, const float* bs, float* out,
                         int Ci, int Hi, int Wi, int Co, int Ho, int Wo) {
    int tilesX = (Wo + 31) / 32, tilesY = (Ho + 31) / 32;
    dim3 g(tilesX * tilesY, Co / CO_BLK, B4);
    conv_tiled_kernel<3, 1, true><<<g, 256>>>(in, wt, bs, out, Ci, Hi, Wi, Co, Ho, Wo, tilesX);
}

extern "C" void kernel_launch(void* const* d_in, const int* in_sizes, int n_in,
                              void* d_out, int out_size)
{
    const float* x   = (const float*)d_in[0];
    const float* w   = (const float*)d_in[1];
    const float* d1w = (const float*)d_in[2];
    const float* d1b = (const float*)d_in[3];
    const float* w2a = (const float*)d_in[4];
    const float* b2a = (const float*)d_in[5];
    const float* w2b = (const float*)d_in[6];
    const float* b2b = (const float*)d_in[7];
    const float* w3a = (const float*)d_in[8];
    const float* b3a = (const float*)d_in[9];
    const float* w3b = (const float*)d_in[10];
    const float* b3b = (const float*)d_in[11];
    const float* w4a = (const float*)d_in[12];
    const float* b4a = (const float*)d_in[13];
    const float* w4b = (const float*)d_in[14];
    const float* b4b = (const float*)d_in[15];
    const float* g4  = (const float*)d_in[16];
    const float* be4 = (const float*)d_in[17];
    const float* u3a = (const float*)d_in[18];
    const float* ub3a= (const float*)d_in[19];
    const float* u3b = (const float*)d_in[20];
    const float* ub3b= (const float*)d_in[21];
    const float* u2a = (const float*)d_in[22];
    const float* ub2a= (const float*)d_in[23];
    const float* u2b = (const float*)d_in[24];
    const float* ub2b= (const float*)d_in[25];
    const float* u1a = (const float*)d_in[26];
    const float* ub1a= (const float*)d_in[27];
    const float* u1b = (const float*)d_in[28];
    const float* ub1b= (const float*)d_in[29];
    const float* wl  = (const float*)d_in[30];
    const float* bl  = (const float*)d_in[31];
    float* out = (float*)d_out;

    float* dyn  = sym(g_dyn);
    float* c1   = sym(g_c1);
    float* p1   = sym(g_p1);
    float* t2   = sym(g_t2);
    float* c2   = sym(g_c2);
    float* p2   = sym(g_p2);
    float* t3   = sym(g_t3);
    float* c3   = sym(g_c3);
    float* p3   = sym(g_p3);
    float* t4   = sym(g_t4);
    float* h4   = sym(g_h4);
    float* cat3 = sym(g_cat3);
    float* u3t  = sym(g_u3t);
    float* u3   = sym(g_u3);
    float* cat2 = sym(g_cat2);
    float* u2t  = sym(g_u2t);
    float* u2   = sym(g_u2);
    float* cat1 = sym(g_cat1);
    float* u1t  = sym(g_u1t);
    float* u1   = sym(g_u1);
    float* bnsc = sym(g_bnscale);
    float* bnsh = sym(g_bnshift);

    // 1. dynamic conv + mish : (4,32,255,255)
    {
        int total = 4 * 32 * 255 * 255;
        dyn_conv_mish_kernel<<<(total + 255) / 256, 256>>>(x, w, dyn);
    }
    // 2. d1 conv (K=4, pad=2) + mish : (4,32,256,256)
    {
        int tilesX = 8;
        dim3 g(tilesX * 8, 32 / CO_BLK, B4);
        conv_tiled_kernel<4, 2, true><<<g, 256>>>(dyn, d1w, d1b, c1, 32, 255, 255, 32, 256, 256, tilesX);
    }
    // 3. pool -> (4,32,128,128)
    {
        int total = 4 * 32 * 128 * 128;
        maxpool_kernel<<<(total + 255) / 256, 256>>>(c1, p1, 32, 256, 256);
    }
    // 4-5. double conv 2 : (4,128,128,128)
    launch_conv3(p1, w2a, b2a, t2, 32, 128, 128, 128, 128, 128);
    launch_conv3(t2, w2b, b2b, c2, 128, 128, 128, 128, 128, 128);
    // 6. pool -> (4,128,64,64)
    {
        int total = 4 * 128 * 64 * 64;
        maxpool_kernel<<<(total + 255) / 256, 256>>>(c2, p2, 128, 128, 128);
    }
    // 7-8. double conv 3 : (4,256,64,64)
    launch_conv3(p2, w3a, b3a, t3, 128, 64, 64, 256, 64, 64);
    launch_conv3(t3, w3b, b3b, c3, 256, 64, 64, 256, 64, 64);
    // 9. pool -> (4,256,32,32)
    {
        int total = 4 * 256 * 32 * 32;
        maxpool_kernel<<<(total + 255) / 256, 256>>>(c3, p3, 256, 64, 64);
    }
    // 10-11. double conv 4 : (4,512,32,32)
    launch_conv3(p3, w4a, b4a, t4, 256, 32, 32, 512, 32, 32);
    launch_conv3(t4, w4b, b4b, h4, 512, 32, 32, 512, 32, 32);
    // 12. batchnorm stats
    bn_stats_kernel<<<512, 256>>>(h4, g4, be4, bnsc, bnsh);
    // 13. upsample(bn(h4)) -> cat3[:, 0:512] at 64x64
    {
        long total = (long)4 * 512 * 64 * 64;
        up2_kernel<<<(int)((total + 255) / 256), 256>>>(h4, cat3, 512, 32, 32, 768, bnsc, bnsh);
    }
    // 14. concat c3 -> cat3[:, 512:768]
    {
        long total = (long)4 * 256 * 64 * 64;
        concat_copy_kernel<<<(int)((total + 255) / 256), 256>>>(c3, cat3, 512, 256, 64 * 64);
    }
    // 15-16. double conv u3 : (4,256,64,64)
    launch_conv3(cat3, u3a, ub3a, u3t, 768, 64, 64, 256, 64, 64);
    launch_conv3(u3t, u3b, ub3b, u3, 256, 64, 64, 256, 64, 64);
    // 17. upsample u3 -> cat2[:, 0:256] at 128x128
    {
        long total = (long)4 * 256 * 128 * 128;
        up2_kernel<<<(int)((total + 255) / 256), 256>>>(u3, cat2, 256, 64, 64, 384, nullptr, nullptr);
    }
    // 18. concat c2 -> cat2[:, 256:384]
    {
        long total = (long)4 * 128 * 128 * 128;
        concat_copy_kernel<<<(int)((total + 255) / 256), 256>>>(c2, cat2, 256, 128, 128 * 128);
    }
    // 19-20. double conv u2 : (4,128,128,128)
    launch_conv3(cat2, u2a, ub2a, u2t, 384, 128, 128, 128, 128, 128);
    launch_conv3(u2t, u2b, ub2b, u2, 128, 128, 128, 128, 128, 128);
    // 21. upsample u2 -> cat1[:, 0:128] at 256x256
    {
        long total = (long)4 * 128 * 256 * 256;
        up2_kernel<<<(int)((total + 255) / 256), 256>>>(u2, cat1, 128, 128, 128, 160, nullptr, nullptr);
    }
    // 22. concat c1 -> cat1[:, 128:160]
    {
        long total = (long)4 * 32 * 256 * 256;
        concat_copy_kernel<<<(int)((total + 255) / 256), 256>>>(c1, cat1, 128, 32, 256 * 256);
    }
    // 23-24. double conv u1 : (4,32,256,256)
    launch_conv3(cat1, u1a, ub1a, u1t, 160, 256, 256, 32, 256, 256);
    launch_conv3(u1t, u1b, ub1b, u1, 32, 256, 256, 32, 256, 256);
    // 25. final 1x1 conv -> (4,1,256,256)
    {
        int total = 4 * 65536;
        conv1x1_kernel<<<(total + 255) / 256, 256>>>(u1, wl, bl, out);
    }
}

// round 5
// speedup vs baseline: 1.0095x; 1.0095x over previous
#include <cuda_runtime.h>
#include <math.h>

// ---------------------------------------------------------------------------
// UNet forward (B=4, H=W=256), fp32 implicit-GEMM convolutions.
// Graph-capturable; all intermediates in __device__ globals.
// ---------------------------------------------------------------------------

#define B4 4

// ---------------- workspace buffers ----------------
__device__ float g_dyn [4*32*255*255];   // dyn conv + mish (255x255)
__device__ float g_p1  [4*32*128*128];
__device__ float g_t2  [4*128*128*128];
__device__ float g_p2  [4*128*64*64];
__device__ float g_t3  [4*256*64*64];
__device__ float g_p3  [4*256*32*32];
__device__ float g_t4  [4*512*32*32];
__device__ float g_h4  [4*512*32*32];
__device__ float g_cat3[4*768*64*64];    // [0:512)=up(bn(h4)), [512:768)=c3
__device__ float g_u3t [4*256*64*64];
__device__ float g_u3  [4*256*64*64];
__device__ float g_cat2[4*384*128*128];  // [0:256)=up(u3), [256:384)=c2
__device__ float g_u2t [4*128*128*128];
__device__ float g_u2  [4*128*128*128];
__device__ float g_cat1[4*160*256*256];  // [0:128)=up(u2), [128:160)=c1
__device__ float g_u1t [4*32*256*256];
__device__ float g_u1  [4*32*256*256];
__device__ float g_bnscale[512];
__device__ float g_bnshift[512];

// Exact identity: tanh(softplus(x)) = t(t+2)/(t(t+2)+2), t = e^x.
__device__ __forceinline__ float mishf(float x) {
    if (x > 15.f) return x;          // tanh(softplus(15)) = 1 - 2e-13
    float t = __expf(x);
    float u = fmaf(t, t, t + t);     // t^2 + 2t
    return x * __fdividef(u, u + 2.f);
}

// ---------------------------------------------------------------------------
// Implicit-GEMM conv: D[pix][co] = sum_{ci,r,s} in[b][ci][oy+r-PAD][ox+s-PAD]
//                                            * w[co][ci][r][s]
// BM=128 pixels, BN=16*TN out-channels, BK=16 K-slice, 256 threads,
// thread tile 8 x TN, double-buffered smem, 1 sync per k-tile.
// Requires: Wo,Ho powers of two (square output), Ci % 16 == 0, Co % BN == 0,
// HoWo % 128 == 0.
// ---------------------------------------------------------------------------
template<int K, int PAD, int TN>
__global__ __launch_bounds__(256, 2)
void conv_gemm_kernel(const float* __restrict__ in,
                      const float* __restrict__ wt,
                      const float* __restrict__ bias,
                      float* __restrict__ outAdj,   // already + coutOff*HoWo
                      int Ci, int Hi, int Wi,
                      int CoutTot,                  // channel stride of output
                      int logWo, int HoWo)
{
    constexpr int BM = 128, BK = 16, BN = 16 * TN;
    __shared__ __align__(16) float As[2][BK][BM];
    __shared__ __align__(16) float Bs[2][BK][BN];

    const int tid = threadIdx.x;
    const int tm = tid & 15, tn = tid >> 4;          // compute-tile coords
    const int aK = tid >> 5, aL = tid & 31;          // A-load coords
    const int kB = tid >> 4, nB = (tid & 15) * TN;   // B-load coords

    const int b = blockIdx.z;
    const int pixBase = blockIdx.x * BM;
    const int coBase = blockIdx.y * BN;

    const int Wo = 1 << logWo;
    const long HiWi = (long)Hi * Wi;
    const float* inB = in + (long)b * Ci * HiWi;

    int oyA[4], oxA[4];
#pragma unroll
    for (int j = 0; j < 4; j++) {
        int pix = pixBase + aL + 32 * j;
        oyA[j] = pix >> logWo;
        oxA[j] = pix & (Wo - 1);
    }

    const int cipt = Ci >> 4;            // Ci/16
    const int KT = K * K * cipt;
    const long wStride = (long)Ci * K * K;

    float acc[8][TN];
#pragma unroll
    for (int mi = 0; mi < 8; mi++)
#pragma unroll
        for (int i = 0; i < TN; i++) acc[mi][i] = 0.f;

    float aReg[8];
    float bReg[TN];

    auto loadTile = [&](int kt) {
        int rs = kt / cipt;
        int cc = kt - rs * cipt;
        int r = rs / K, s = rs - r * K;
        int ciB = cc * 16;
#pragma unroll
        for (int j = 0; j < 4; j++) {
            int gy = oyA[j] + r - PAD;
            int gx = oxA[j] + s - PAD;
            bool v = ((unsigned)gy < (unsigned)Hi) && ((unsigned)gx < (unsigned)Wi);
            const float* p = inB + (ciB + aK) * HiWi + (long)gy * Wi + gx;
            aReg[j]     = v ? __ldg(p) : 0.f;
            aReg[4 + j] = v ? __ldg(p + 8 * HiWi) : 0.f;
        }
        const float* wp = wt + (long)(coBase + nB) * wStride + (ciB + kB) * (K * K) + rs;
#pragma unroll
        for (int i = 0; i < TN; i++) bReg[i] = __ldg(wp + i * wStride);
    };
    auto stsTile = [&](int buf) {
#pragma unroll
        for (int j = 0; j < 4; j++) {
            As[buf][aK    ][aL + 32 * j] = aReg[j];
            As[buf][aK + 8][aL + 32 * j] = aReg[4 + j];
        }
#pragma unroll
        for (int i = 0; i < TN; i++) Bs[buf][kB][nB + i] = bReg[i];
    };

    loadTile(0);
    stsTile(0);
    __syncthreads();

    for (int kt = 0; kt < KT; kt++) {
        const int cur = kt & 1, nxt = cur ^ 1;
        if (kt + 1 < KT) loadTile(kt + 1);
#pragma unroll
        for (int kk = 0; kk < BK; kk++) {
            float4 a0 = *(const float4*)&As[cur][kk][tm * 4];
            float4 a1 = *(const float4*)&As[cur][kk][64 + tm * 4];
            float bf[TN];
#pragma unroll
            for (int i = 0; i < TN; i++) bf[i] = Bs[cur][kk][tn * TN + i];
#pragma unroll
            for (int i = 0; i < TN; i++) {
                acc[0][i] = fmaf(a0.x, bf[i], acc[0][i]);
                acc[1][i] = fmaf(a0.y, bf[i], acc[1][i]);
                acc[2][i] = fmaf(a0.z, bf[i], acc[2][i]);
                acc[3][i] = fmaf(a0.w, bf[i], acc[3][i]);
                acc[4][i] = fmaf(a1.x, bf[i], acc[4][i]);
                acc[5][i] = fmaf(a1.y, bf[i], acc[5][i]);
                acc[6][i] = fmaf(a1.z, bf[i], acc[6][i]);
                acc[7][i] = fmaf(a1.w, bf[i], acc[7][i]);
            }
        }
        if (kt + 1 < KT) stsTile(nxt);
        __syncthreads();
    }

    // epilogue: bias + mish, vectorized stores
#pragma unroll
    for (int i = 0; i < TN; i++) {
        int co = coBase + tn * TN + i;
        float bi = bias[co];
        float* o = outAdj + ((long)b * CoutTot + co) * HoWo + pixBase;
        float4 v0, v1;
        v0.x = mishf(acc[0][i] + bi);
        v0.y = mishf(acc[1][i] + bi);
        v0.z = mishf(acc[2][i] + bi);
        v0.w = mishf(acc[3][i] + bi);
        v1.x = mishf(acc[4][i] + bi);
        v1.y = mishf(acc[5][i] + bi);
        v1.z = mishf(acc[6][i] + bi);
        v1.w = mishf(acc[7][i] + bi);
        *(float4*)(o + tm * 4) = v0;
        *(float4*)(o + 64 + tm * 4) = v1;
    }
}

// ---------------- dynamic per-sample conv (K=4, pad=1) + mish ----------------
__global__ void dyn_conv_mish_kernel(const float* __restrict__ x,
                                     const float* __restrict__ w,
                                     float* __restrict__ out)
{
    const int Ho = 255, Wo = 255, Hi = 256, Wi = 256;
    int idx = blockIdx.x * blockDim.x + threadIdx.x;
    int total = 4 * 32 * Ho * Wo;
    if (idx >= total) return;
    int ox = idx % Wo;
    int t = idx / Wo;
    int oy = t % Ho; t /= Ho;
    int co = t % 32; int b = t / 32;
    const float* xb = x + b * Hi * Wi;
    const float* wb = w + (b * 32 + co) * 16;
    float acc = 0.f;
#pragma unroll
    for (int ky = 0; ky < 4; ky++) {
        int iy = oy - 1 + ky;
        if (iy < 0 || iy >= Hi) continue;
#pragma unroll
        for (int kx = 0; kx < 4; kx++) {
            int ix = ox - 1 + kx;
            if (ix < 0 || ix >= Wi) continue;
            acc = fmaf(xb[iy * Wi + ix], wb[ky * 4 + kx], acc);
        }
    }
    out[idx] = mishf(acc);
}

// ---------------- 2x2 maxpool (strided-channel input) ----------------
__global__ void maxpool_kernel(const float* __restrict__ in, float* __restrict__ out,
                               int C, int CinTot, int cinOff, int Hi, int Wi)
{
    int Ho = Hi >> 1, Wo = Wi >> 1;
    int idx = blockIdx.x * blockDim.x + threadIdx.x;
    int total = B4 * C * Ho * Wo;
    if (idx >= total) return;
    int ox = idx % Wo;
    int t = idx / Wo;
    int oy = t % Ho; t /= Ho;
    int c = t % C; int b = t / C;
    const float* p = in + ((long)b * CinTot + cinOff + c) * Hi * Wi + (oy * 2) * Wi + ox * 2;
    float v0 = p[0], v1 = p[1], v2 = p[Wi], v3 = p[Wi + 1];
    out[idx] = fmaxf(fmaxf(v0, v1), fmaxf(v2, v3));
}

// ---------------- batchnorm stats (per-channel over B,H,W) ----------------
__global__ void bn_stats_kernel(const float* __restrict__ h,
                                const float* __restrict__ g,
                                const float* __restrict__ be,
                                float* __restrict__ scale,
                                float* __restrict__ shift)
{
    __shared__ float ss[256], ss2[256];
    int c = blockIdx.x;
    int tid = threadIdx.x;
    float s = 0.f, s2 = 0.f;
    for (int b = 0; b < 4; b++) {
        const float* p = h + ((long)b * 512 + c) * 1024;
        for (int i = tid; i < 1024; i += 256) {
            float v = p[i];
            s += v; s2 += v * v;
        }
    }
    ss[tid] = s; ss2[tid] = s2;
    __syncthreads();
    for (int off = 128; off > 0; off >>= 1) {
        if (tid < off) { ss[tid] += ss[tid + off]; ss2[tid] += ss2[tid + off]; }
        __syncthreads();
    }
    if (tid == 0) {
        float mean = ss[0] * (1.f / 4096.f);
        float var = ss2[0] * (1.f / 4096.f) - mean * mean;
        float sc = g[c] * rsqrtf(var + 1e-5f);
        scale[c] = sc;
        shift[c] = be[c] - mean * sc;
    }
}

// ---------------- bilinear x2 upsample (align_corners=True), optional BN ----
__global__ void up2_kernel(const float* __restrict__ in, float* __restrict__ outbase,
                           int C, int H, int W, int Ccat,
                           const float* __restrict__ scale,
                           const float* __restrict__ shift)
{
    int Ho = 2 * H, Wo = 2 * W;
    long idx = (long)blockIdx.x * blockDim.x + threadIdx.x;
    long total = (long)B4 * C * Ho * Wo;
    if (idx >= total) return;
    int ox = idx % Wo;
    long t = idx / Wo;
    int oy = t % Ho; t /= Ho;
    int c = t % C; int b = (int)(t / C);

    float ry = (float)((double)(H - 1) / (double)(Ho - 1));
    float rx = (float)((double)(W - 1) / (double)(Wo - 1));
    float sy = (float)oy * ry;
    float sx = (float)ox * rx;
    int y0 = (int)floorf(sy);
    int x0 = (int)floorf(sx);
    float fy = sy - (float)y0;
    float fx = sx - (float)x0;
    int y1 = min(y0 + 1, H - 1);
    int x1 = min(x0 + 1, W - 1);

    const float* inC = in + ((long)b * C + c) * H * W;
    float a0 = inC[y0 * W + x0] * (1.f - fy) + inC[y1 * W + x0] * fy;
    float a1 = inC[y0 * W + x1] * (1.f - fy) + inC[y1 * W + x1] * fy;
    float v = a0 * (1.f - fx) + a1 * fx;
    if (scale) v = v * scale[c] + shift[c];
    outbase[((long)b * Ccat + c) * Ho * Wo + (long)oy * Wo + ox] = v;
}

// ---------------- final 1x1 conv (32 -> 1) ----------------
__global__ void conv1x1_kernel(const float* __restrict__ in,
                               const float* __restrict__ w,
                               const float* __restrict__ bias,
                               float* __restrict__ out)
{
    int idx = blockIdx.x * blockDim.x + threadIdx.x;
    int total = 4 * 65536;
    if (idx >= total) return;
    int hw = idx & 65535;
    int b = idx >> 16;
    float acc = bias[0];
    const float* p = in + (long)b * 32 * 65536 + hw;
#pragma unroll
    for (int ci = 0; ci < 32; ci++) acc = fmaf(p[(long)ci * 65536], w[ci], acc);
    out[idx] = acc;
}

// ---------------------------------------------------------------------------
// Host side
// ---------------------------------------------------------------------------
static float* sym(const void* symbol) {
    void* p = nullptr;
    cudaGetSymbolAddress(&p, symbol);
    return (float*)p;
}

template<int K, int PAD, int TN>
static void launch_cg(const float* in, const float* wt, const float* bs,
                      float* out, int coutOff,
                      int Ci, int Hi, int Wi, int Co, int CoutTot, int logWo)
{
    const int HoWo = 1 << (2 * logWo);
    const int BN = 16 * TN;
    dim3 g(HoWo / 128, Co / BN, B4);
    conv_gemm_kernel<K, PAD, TN><<<g, 256>>>(in, wt, bs,
        out + (long)coutOff * HoWo, Ci, Hi, Wi, CoutTot, logWo, HoWo);
}

extern "C" void kernel_launch(void* const* d_in, const int* in_sizes, int n_in,
                              void* d_out, int out_size)
{
    const float* x   = (const float*)d_in[0];
    const float* w   = (const float*)d_in[1];
    const float* d1w = (const float*)d_in[2];
    const float* d1b = (const float*)d_in[3];
    const float* w2a = (const float*)d_in[4];
    const float* b2a = (const float*)d_in[5];
    const float* w2b = (const float*)d_in[6];
    const float* b2b = (const float*)d_in[7];
    const float* w3a = (const float*)d_in[8];
    const float* b3a = (const float*)d_in[9];
    const float* w3b = (const float*)d_in[10];
    const float* b3b = (const float*)d_in[11];
    const float* w4a = (const float*)d_in[12];
    const float* b4a = (const float*)d_in[13];
    const float* w4b = (const float*)d_in[14];
    const float* b4b = (const float*)d_in[15];
    const float* g4  = (const float*)d_in[16];
    const float* be4 = (const float*)d_in[17];
    const float* u3a = (const float*)d_in[18];
    const float* ub3a= (const float*)d_in[19];
    const float* u3b = (const float*)d_in[20];
    const float* ub3b= (const float*)d_in[21];
    const float* u2a = (const float*)d_in[22];
    const float* ub2a= (const float*)d_in[23];
    const float* u2b = (const float*)d_in[24];
    const float* ub2b= (const float*)d_in[25];
    const float* u1a = (const float*)d_in[26];
    const float* ub1a= (const float*)d_in[27];
    const float* u1b = (const float*)d_in[28];
    const float* ub1b= (const float*)d_in[29];
    const float* wl  = (const float*)d_in[30];
    const float* bl  = (const float*)d_in[31];
    float* out = (float*)d_out;

    float* dyn  = sym(g_dyn);
    float* p1   = sym(g_p1);
    float* t2   = sym(g_t2);
    float* p2   = sym(g_p2);
    float* t3   = sym(g_t3);
    float* p3   = sym(g_p3);
    float* t4   = sym(g_t4);
    float* h4   = sym(g_h4);
    float* cat3 = sym(g_cat3);
    float* u3t  = sym(g_u3t);
    float* u3   = sym(g_u3);
    float* cat2 = sym(g_cat2);
    float* u2t  = sym(g_u2t);
    float* u2   = sym(g_u2);
    float* cat1 = sym(g_cat1);
    float* u1t  = sym(g_u1t);
    float* u1   = sym(g_u1);
    float* bnsc = sym(g_bnscale);
    float* bnsh = sym(g_bnshift);

    // 1. dynamic conv + mish : (4,32,255,255)
    {
        int total = 4 * 32 * 255 * 255;
        dyn_conv_mish_kernel<<<(total + 255) / 256, 256>>>(x, w, dyn);
    }
    // 2. d1 conv (K=4, pad=2) + mish : c1 -> cat1[:, 128:160] @ 256x256
    launch_cg<4, 2, 2>(dyn, d1w, d1b, cat1, 128, 32, 255, 255, 32, 160, 8);
    // 3. pool c1 -> (4,32,128,128)
    {
        int total = 4 * 32 * 128 * 128;
        maxpool_kernel<<<(total + 255) / 256, 256>>>(cat1, p1, 32, 160, 128, 256, 256);
    }
    // 4-5. double conv 2 : c2 -> cat2[:, 256:384] @ 128x128
    launch_cg<3, 1, 8>(p1, w2a, b2a, t2, 0, 32, 128, 128, 128, 128, 7);
    launch_cg<3, 1, 8>(t2, w2b, b2b, cat2, 256, 128, 128, 128, 128, 384, 7);
    // 6. pool c2 -> (4,128,64,64)
    {
        int total = 4 * 128 * 64 * 64;
        maxpool_kernel<<<(total + 255) / 256, 256>>>(cat2, p2, 128, 384, 256, 128, 128);
    }
    // 7-8. double conv 3 : c3 -> cat3[:, 512:768] @ 64x64
    launch_cg<3, 1, 8>(p2, w3a, b3a, t3, 0, 128, 64, 64, 256, 256, 6);
    launch_cg<3, 1, 8>(t3, w3b, b3b, cat3, 512, 256, 64, 64, 256, 768, 6);
    // 9. pool c3 -> (4,256,32,32)
    {
        int total = 4 * 256 * 32 * 32;
        maxpool_kernel<<<(total + 255) / 256, 256>>>(cat3, p3, 256, 768, 512, 64, 64);
    }
    // 10-11. double conv 4 : (4,512,32,32)
    launch_cg<3, 1, 4>(p3, w4a, b4a, t4, 0, 256, 32, 32, 512, 512, 5);
    launch_cg<3, 1, 4>(t4, w4b, b4b, h4, 0, 512, 32, 32, 512, 512, 5);
    // 12. batchnorm stats
    bn_stats_kernel<<<512, 256>>>(h4, g4, be4, bnsc, bnsh);
    // 13. upsample(bn(h4)) -> cat3[:, 0:512] @ 64x64
    {
        long total = (long)4 * 512 * 64 * 64;
        up2_kernel<<<(int)((total + 255) / 256), 256>>>(h4, cat3, 512, 32, 32, 768, bnsc, bnsh);
    }
    // 14-15. double conv u3 : (4,256,64,64)
    launch_cg<3, 1, 8>(cat3, u3a, ub3a, u3t, 0, 768, 64, 64, 256, 256, 6);
    launch_cg<3, 1, 8>(u3t, u3b, ub3b, u3, 0, 256, 64, 64, 256, 256, 6);
    // 16. upsample u3 -> cat2[:, 0:256] @ 128x128
    {
        long total = (long)4 * 256 * 128 * 128;
        up2_kernel<<<(int)((total + 255) / 256), 256>>>(u3, cat2, 256, 64, 64, 384, nullptr, nullptr);
    }
    // 17-18. double conv u2 : (4,128,128,128)
    launch_cg<3, 1, 8>(cat2, u2a, ub2a, u2t, 0, 384, 128, 128, 128, 128, 7);
    launch_cg<3, 1, 8>(u2t, u2b, ub2b, u2, 0, 128, 128, 128, 128, 128, 7);
    // 19. upsample u2 -> cat1[:, 0:128] @ 256x256
    {
        long total = (long)4 * 128 * 256 * 256;
        up2_kernel<<<(int)((total + 255) / 256), 256>>>(u2, cat1, 128, 128, 128, 160, nullptr, nullptr);
    }
    // 20-21. double conv u1 : (4,32,256,256)
    launch_cg<3, 1, 2>(cat1, u1a, ub1a, u1t, 0, 160, 256, 256, 32, 32, 8);
    launch_cg<3, 1, 2>(u1t, u1b, ub1b, u1, 0, 32, 256, 256, 32, 32, 8);
    // 22. final 1x1 conv -> (4,1,256,256)
    {
        int total = 4 * 65536;
        conv1x1_kernel<<<(total + 255) / 256, 256>>>(u1, wl, bl, out);
    }
}

// round 9
// speedup vs baseline: 2.7044x; 2.6790x over previous
#include <cuda_runtime.h>
#include <stdint.h>
#include <math.h>

// ---------------------------------------------------------------------------
// UNet forward (B=4, 256x256): convolutions on tensor cores via portable
// mma.sync m16n8k8 tf32 (sm_80+ path; no sm_103a-only features).
// Graph-capturable; all intermediates in __device__ globals.
// ---------------------------------------------------------------------------

#define B4 4

// ---------------- workspace buffers ----------------
__device__ float g_dyn [4*32*255*255];
__device__ float g_p1  [4*32*128*128];
__device__ float g_t2  [4*128*128*128];
__device__ float g_p2  [4*128*64*64];
__device__ float g_t3  [4*256*64*64];
__device__ float g_p3  [4*256*32*32];
__device__ float g_t4  [4*512*32*32];
__device__ float g_h4  [4*512*32*32];
__device__ float g_cat3[4*768*64*64];    // [0:512)=up(bn(h4)), [512:768)=c3
__device__ float g_u3t [4*256*64*64];
__device__ float g_u3  [4*256*64*64];
__device__ float g_cat2[4*384*128*128];  // [0:256)=up(u3), [256:384)=c2
__device__ float g_u2t [4*128*128*128];
__device__ float g_u2  [4*128*128*128];
__device__ float g_cat1[4*160*256*256];  // [0:128)=up(u2), [128:160)=c1
__device__ float g_u1t [4*32*256*256];
__device__ float g_u1  [4*32*256*256];
__device__ float g_bnscale[512];
__device__ float g_bnshift[512];
__device__ __align__(16) float g_wt[512*512*9];   // transposed tf32 weights

// Exact identity: tanh(softplus(x)) = t(t+2)/(t(t+2)+2), t = e^x.
__device__ __forceinline__ float mishf(float x) {
    if (x > 15.f) return x;
    float t = __expf(x);
    float u = fmaf(t, t, t + t);
    return x * __fdividef(u, u + 2.f);
}

__device__ __forceinline__ uint32_t to_tf32(float f) {
    uint32_t v;
    asm("cvt.rna.tf32.f32 %0, %1;" : "=r"(v) : "f"(f));
    return v;
}

__device__ __forceinline__ void mma_tf32(float& d0, float& d1, float& d2, float& d3,
                                         uint32_t a0, uint32_t a1, uint32_t a2, uint32_t a3,
                                         uint32_t b0, uint32_t b1) {
    asm volatile("mma.sync.aligned.m16n8k8.row.col.f32.tf32.tf32.f32 "
                 "{%0,%1,%2,%3}, {%4,%5,%6,%7}, {%8,%9}, {%0,%1,%2,%3};"
                 : "+f"(d0), "+f"(d1), "+f"(d2), "+f"(d3)
                 : "r"(a0), "r"(a1), "r"(a2), "r"(a3), "r"(b0), "r"(b1));
}

// ---------------------------------------------------------------------------
// Weight transform: w[co][ci][rs] (fp32) -> wt[co][rs][ci] (tf32-rounded fp32)
// ---------------------------------------------------------------------------
__global__ void wtrans_kernel(const float* __restrict__ w, float* __restrict__ o,
                              int Ci, int KK, int total)
{
    int idx = blockIdx.x * blockDim.x + threadIdx.x;
    if (idx >= total) return;
    int cikk = Ci * KK;
    int co = idx / cikk;
    int rem = idx - co * cikk;
    int ci = rem / KK;
    int rs = rem - ci * KK;
    o[(co * KK + rs) * Ci + ci] = __uint_as_float(to_tf32(w[idx]));
}

// ---------------------------------------------------------------------------
// Implicit-GEMM conv on mma.sync tf32.
// M=128 pixels, N=BN out-chan, BK=32 K-slice (one (r,s), 32 input channels).
// 256 threads = 8 warps; BN=64: warp grid 4x2 (32x32 warp tile);
//                        BN=32: warp grid 8x1 (16x32 warp tile).
// Requires Ci%32==0, Co%BN==0, HoWo%128==0, Ho=Wo=2^logWo.
// ---------------------------------------------------------------------------
template<int K, int PAD, int BN>
__global__ __launch_bounds__(256)
void conv_mma_kernel(const float* __restrict__ in,
                     const float* __restrict__ wtT,   // [Co][K*K][Ci] tf32
                     const float* __restrict__ bias,
                     float* __restrict__ outAdj,
                     int Ci, int Hi, int Wi,
                     int CoutTot, int logWo, int HoWo)
{
    constexpr int BM = 128, BK = 32;
    constexpr int SA = BM + 8;                 // A row stride (floats)
    constexpr int SB = BN + 8;                 // B row stride
    constexpr int WN = BN / 32;                // warps along N
    constexpr int WM = 8 / WN;                 // warps along M
    constexpr int WTM = BM / WM;               // warp tile M (32 or 16)
    constexpr int MMA_M = WTM / 16;            // 2 or 1
    constexpr int NB4 = (BN * BK / 4) / 256;   // float4 B loads per thread (2 or 1)
    constexpr int LOGBN = (BN == 64) ? 6 : 5;

    extern __shared__ float sm[];
    float* As = sm;                            // [2][BK][SA]
    float* Bs = sm + 2 * BK * SA;              // [2][BK][SB]

    const int tid = threadIdx.x;
    const int warpId = tid >> 5;
    const int lane = tid & 31;
    const int warpN = (WN == 2) ? (warpId & 1) : 0;
    const int warpM = (WN == 2) ? (warpId >> 1) : warpId;
    const int row = lane >> 2;                 // 0..7
    const int colk = lane & 3;                 // 0..3

    const int b = blockIdx.z;
    const int pixBase = blockIdx.x * BM;
    const int coBase = blockIdx.y * BN;
    const int Wo = 1 << logWo;

    const int m = tid & 127;
    const int g = tid >> 7;                    // 0/1: which 16 k's this thread gathers
    const int pix = pixBase + m;
    const int oy = pix >> logWo;
    const int ox = pix & (Wo - 1);
    const long HiWi = (long)Hi * Wi;
    const float* inB = in + (long)b * Ci * HiWi;
    const int Ktot = K * K * Ci;
    const int cipt = Ci >> 5;
    const int KT = Ktot >> 5;

    float acc[MMA_M][4][4];
#pragma unroll
    for (int mi = 0; mi < MMA_M; mi++)
#pragma unroll
        for (int ni = 0; ni < 4; ni++)
#pragma unroll
            for (int i = 0; i < 4; i++) acc[mi][ni][i] = 0.f;

    uint32_t aR[16];
    float4 bR[NB4];

    auto loadGlobal = [&](int kt) {
        int rs = kt / cipt;
        int cb = (kt - rs * cipt) << 5;
        int r = rs / K, s = rs - r * K;
        int gy = oy + r - PAD;
        int gx = ox + s - PAD;
        bool ok = ((unsigned)gy < (unsigned)Hi) && ((unsigned)gx < (unsigned)Wi);
        const float* rowp = inB + (long)cb * HiWi + (long)gy * Wi + gx;
#pragma unroll
        for (int j = 0; j < 16; j++)
            aR[j] = ok ? to_tf32(__ldg(rowp + (long)(g * 16 + j) * HiWi)) : 0u;
#pragma unroll
        for (int it = 0; it < NB4; it++) {
            int idx = tid + it * 256;
            int n = idx & (BN - 1);
            int k0 = (idx >> LOGBN) * 4;
            bR[it] = *(const float4*)(wtT + (long)(coBase + n) * Ktot + kt * 32 + k0);
        }
    };
    auto storeSmem = [&](int buf) {
        float* Ab = As + buf * BK * SA;
#pragma unroll
        for (int j = 0; j < 16; j++)
            Ab[(g * 16 + j) * SA + m] = __uint_as_float(aR[j]);
        float* Bb = Bs + buf * BK * SB;
#pragma unroll
        for (int it = 0; it < NB4; it++) {
            int idx = tid + it * 256;
            int n = idx & (BN - 1);
            int k0 = (idx >> LOGBN) * 4;
            Bb[(k0 + 0) * SB + n] = bR[it].x;
            Bb[(k0 + 1) * SB + n] = bR[it].y;
            Bb[(k0 + 2) * SB + n] = bR[it].z;
            Bb[(k0 + 3) * SB + n] = bR[it].w;
        }
    };
    auto compute = [&](int buf) {
        const float* Ab = As + buf * BK * SA;
        const float* Bb = Bs + buf * BK * SB;
#pragma unroll
        for (int ks = 0; ks < 4; ks++) {
            const int kb = ks * 8;
            uint32_t af[MMA_M][4];
#pragma unroll
            for (int mi = 0; mi < MMA_M; mi++) {
                int m0 = warpM * WTM + mi * 16 + row;
                af[mi][0] = __float_as_uint(Ab[(kb + colk) * SA + m0]);
                af[mi][1] = __float_as_uint(Ab[(kb + colk) * SA + m0 + 8]);
                af[mi][2] = __float_as_uint(Ab[(kb + colk + 4) * SA + m0]);
                af[mi][3] = __float_as_uint(Ab[(kb + colk + 4) * SA + m0 + 8]);
            }
            uint32_t bf[4][2];
#pragma unroll
            for (int ni = 0; ni < 4; ni++) {
                int n0 = warpN * 32 + ni * 8 + (lane >> 2);
                bf[ni][0] = __float_as_uint(Bb[(kb + colk) * SB + n0]);
                bf[ni][1] = __float_as_uint(Bb[(kb + colk + 4) * SB + n0]);
            }
#pragma unroll
            for (int mi = 0; mi < MMA_M; mi++)
#pragma unroll
                for (int ni = 0; ni < 4; ni++)
                    mma_tf32(acc[mi][ni][0], acc[mi][ni][1], acc[mi][ni][2], acc[mi][ni][3],
                             af[mi][0], af[mi][1], af[mi][2], af[mi][3],
                             bf[ni][0], bf[ni][1]);
        }
    };

    loadGlobal(0);
    storeSmem(0);
    __syncthreads();

    for (int kt = 0; kt < KT; kt++) {
        const int cur = kt & 1;
        if (kt + 1 < KT) loadGlobal(kt + 1);
        compute(cur);
        if (kt + 1 < KT) storeSmem(cur ^ 1);
        __syncthreads();
    }

    // epilogue: c0/c1 at (row, 2*colk /+1), c2/c3 at row+8
#pragma unroll
    for (int mi = 0; mi < MMA_M; mi++) {
#pragma unroll
        for (int ni = 0; ni < 4; ni++) {
            int pixr = pixBase + warpM * WTM + mi * 16 + row;
            int co = coBase + warpN * 32 + ni * 8 + 2 * colk;
            float bi0 = __ldg(bias + co);
            float bi1 = __ldg(bias + co + 1);
            float* o0 = outAdj + ((long)b * CoutTot + co) * HoWo;
            float* o1 = o0 + HoWo;
            o0[pixr]     = mishf(acc[mi][ni][0] + bi0);
            o1[pixr]     = mishf(acc[mi][ni][1] + bi1);
            o0[pixr + 8] = mishf(acc[mi][ni][2] + bi0);
            o1[pixr + 8] = mishf(acc[mi][ni][3] + bi1);
        }
    }
}

// ---------------- dynamic per-sample conv (K=4, pad=1) + mish ----------------
__global__ void dyn_conv_mish_kernel(const float* __restrict__ x,
                                     const float* __restrict__ w,
                                     float* __restrict__ out)
{
    const int Ho = 255, Wo = 255, Hi = 256, Wi = 256;
    int idx = blockIdx.x * blockDim.x + threadIdx.x;
    int total = 4 * 32 * Ho * Wo;
    if (idx >= total) return;
    int ox = idx % Wo;
    int t = idx / Wo;
    int oy = t % Ho; t /= Ho;
    int co = t % 32; int b = t / 32;
    const float* xb = x + b * Hi * Wi;
    const float* wb = w + (b * 32 + co) * 16;
    float acc = 0.f;
#pragma unroll
    for (int ky = 0; ky < 4; ky++) {
        int iy = oy - 1 + ky;
        if (iy < 0 || iy >= Hi) continue;
#pragma unroll
        for (int kx = 0; kx < 4; kx++) {
            int ix = ox - 1 + kx;
            if (ix < 0 || ix >= Wi) continue;
            acc = fmaf(xb[iy * Wi + ix], wb[ky * 4 + kx], acc);
        }
    }
    out[idx] = mishf(acc);
}

// ---------------- 2x2 maxpool (strided-channel input) ----------------
__global__ void maxpool_kernel(const float* __restrict__ in, float* __restrict__ out,
                               int C, int CinTot, int cinOff, int Hi, int Wi)
{
    int Ho = Hi >> 1, Wo = Wi >> 1;
    int idx = blockIdx.x * blockDim.x + threadIdx.x;
    int total = B4 * C * Ho * Wo;
    if (idx >= total) return;
    int ox = idx % Wo;
    int t = idx / Wo;
    int oy = t % Ho; t /= Ho;
    int c = t % C; int b = t / C;
    const float* p = in + ((long)b * CinTot + cinOff + c) * Hi * Wi + (oy * 2) * Wi + ox * 2;
    float v0 = p[0], v1 = p[1], v2 = p[Wi], v3 = p[Wi + 1];
    out[idx] = fmaxf(fmaxf(v0, v1), fmaxf(v2, v3));
}

// ---------------- batchnorm stats ----------------
__global__ void bn_stats_kernel(const float* __restrict__ h,
                                const float* __restrict__ g,
                                const float* __restrict__ be,
                                float* __restrict__ scale,
                                float* __restrict__ shift)
{
    __shared__ float ss[256], ss2[256];
    int c = blockIdx.x;
    int tid = threadIdx.x;
    float s = 0.f, s2 = 0.f;
    for (int b = 0; b < 4; b++) {
        const float* p = h + ((long)b * 512 + c) * 1024;
        for (int i = tid; i < 1024; i += 256) {
            float v = p[i];
            s += v; s2 += v * v;
        }
    }
    ss[tid] = s; ss2[tid] = s2;
    __syncthreads();
    for (int off = 128; off > 0; off >>= 1) {
        if (tid < off) { ss[tid] += ss[tid + off]; ss2[tid] += ss2[tid + off]; }
        __syncthreads();
    }
    if (tid == 0) {
        float mean = ss[0] * (1.f / 4096.f);
        float var = ss2[0] * (1.f / 4096.f) - mean * mean;
        float sc = g[c] * rsqrtf(var + 1e-5f);
        scale[c] = sc;
        shift[c] = be[c] - mean * sc;
    }
}

// ---------------- bilinear x2 upsample (align_corners=True), optional BN ----
__global__ void up2_kernel(const float* __restrict__ in, float* __restrict__ outbase,
                           int C, int H, int W, int Ccat,
                           const float* __restrict__ scale,
                           const float* __restrict__ shift)
{
    int Ho = 2 * H, Wo = 2 * W;
    long idx = (long)blockIdx.x * blockDim.x + threadIdx.x;
    long total = (long)B4 * C * Ho * Wo;
    if (idx >= total) return;
    int ox = idx % Wo;
    long t = idx / Wo;
    int oy = t % Ho; t /= Ho;
    int c = t % C; int b = (int)(t / C);

    float ry = (float)((double)(H - 1) / (double)(Ho - 1));
    float rx = (float)((double)(W - 1) / (double)(Wo - 1));
    float sy = (float)oy * ry;
    float sx = (float)ox * rx;
    int y0 = (int)floorf(sy);
    int x0 = (int)floorf(sx);
    float fy = sy - (float)y0;
    float fx = sx - (float)x0;
    int y1 = min(y0 + 1, H - 1);
    int x1 = min(x0 + 1, W - 1);

    const float* inC = in + ((long)b * C + c) * H * W;
    float a0 = inC[y0 * W + x0] * (1.f - fy) + inC[y1 * W + x0] * fy;
    float a1 = inC[y0 * W + x1] * (1.f - fy) + inC[y1 * W + x1] * fy;
    float v = a0 * (1.f - fx) + a1 * fx;
    if (scale) v = v * scale[c] + shift[c];
    outbase[((long)b * Ccat + c) * Ho * Wo + (long)oy * Wo + ox] = v;
}

// ---------------- final 1x1 conv (32 -> 1) ----------------
__global__ void conv1x1_kernel(const float* __restrict__ in,
                               const float* __restrict__ w,
                               const float* __restrict__ bias,
                               float* __restrict__ out)
{
    int idx = blockIdx.x * blockDim.x + threadIdx.x;
    int total = 4 * 65536;
    if (idx >= total) return;
    int hw = idx & 65535;
    int b = idx >> 16;
    float acc = bias[0];
    const float* p = in + (long)b * 32 * 65536 + hw;
#pragma unroll
    for (int ci = 0; ci < 32; ci++) acc = fmaf(p[(long)ci * 65536], w[ci], acc);
    out[idx] = acc;
}

// ---------------------------------------------------------------------------
// Host side
// ---------------------------------------------------------------------------
static float* sym(const void* symbol) {
    void* p = nullptr;
    cudaGetSymbolAddress(&p, symbol);
    return (float*)p;
}

template<int K, int PAD, int BN>
static void conv_mma(const float* in, const float* w, const float* bs,
                     float* out, int coutOff,
                     int Ci, int Hi, int Wi, int Co, int CoutTot, int logWo,
                     float* wscr)
{
    const int KK = K * K;
    const int tot = Co * Ci * KK;
    wtrans_kernel<<<(tot + 255) / 256, 256>>>(w, wscr, Ci, KK, tot);
    const int HoWo = 1 << (2 * logWo);
    const size_t smem = (2 * 32 * (128 + 8) + 2 * 32 * (BN + 8)) * sizeof(float);
    cudaFuncSetAttribute(conv_mma_kernel<K, PAD, BN>,
                         cudaFuncAttributeMaxDynamicSharedMemorySize, (int)smem);
    dim3 g(HoWo / 128, Co / BN, B4);
    conv_mma_kernel<K, PAD, BN><<<g, 256, smem>>>(in, wscr, bs,
        out + (long)coutOff * HoWo, Ci, Hi, Wi, CoutTot, logWo, HoWo);
}

extern "C" void kernel_launch(void* const* d_in, const int* in_sizes, int n_in,
                              void* d_out, int out_size)
{
    const float* x   = (const float*)d_in[0];
    const float* w   = (const float*)d_in[1];
    const float* d1w = (const float*)d_in[2];
    const float* d1b = (const float*)d_in[3];
    const float* w2a = (const float*)d_in[4];
    const float* b2a = (const float*)d_in[5];
    const float* w2b = (const float*)d_in[6];
    const float* b2b = (const float*)d_in[7];
    const float* w3a = (const float*)d_in[8];
    const float* b3a = (const float*)d_in[9];
    const float* w3b = (const float*)d_in[10];
    const float* b3b = (const float*)d_in[11];
    const float* w4a = (const float*)d_in[12];
    const float* b4a = (const float*)d_in[13];
    const float* w4b = (const float*)d_in[14];
    const float* b4b = (const float*)d_in[15];
    const float* g4  = (const float*)d_in[16];
    const float* be4 = (const float*)d_in[17];
    const float* u3a = (const float*)d_in[18];
    const float* ub3a= (const float*)d_in[19];
    const float* u3b = (const float*)d_in[20];
    const float* ub3b= (const float*)d_in[21];
    const float* u2a = (const float*)d_in[22];
    const float* ub2a= (const float*)d_in[23];
    const float* u2b = (const float*)d_in[24];
    const float* ub2b= (const float*)d_in[25];
    const float* u1a = (const float*)d_in[26];
    const float* ub1a= (const float*)d_in[27];
    const float* u1b = (const float*)d_in[28];
    const float* ub1b= (const float*)d_in[29];
    const float* wl  = (const float*)d_in[30];
    const float* bl  = (const float*)d_in[31];
    float* out = (float*)d_out;

    float* dyn  = sym(g_dyn);
    float* p1   = sym(g_p1);
    float* t2   = sym(g_t2);
    float* p2   = sym(g_p2);
    float* t3   = sym(g_t3);
    float* p3   = sym(g_p3);
    float* t4   = sym(g_t4);
    float* h4   = sym(g_h4);
    float* cat3 = sym(g_cat3);
    float* u3t  = sym(g_u3t);
    float* u3   = sym(g_u3);
    float* cat2 = sym(g_cat2);
    float* u2t  = sym(g_u2t);
    float* u2   = sym(g_u2);
    float* cat1 = sym(g_cat1);
    float* u1t  = sym(g_u1t);
    float* u1   = sym(g_u1);
    float* bnsc = sym(g_bnscale);
    float* bnsh = sym(g_bnshift);
    float* wscr = sym(g_wt);

    // 1. dynamic conv + mish : (4,32,255,255)
    {
        int total = 4 * 32 * 255 * 255;
        dyn_conv_mish_kernel<<<(total + 255) / 256, 256>>>(x, w, dyn);
    }
    // 2. d1 conv (K=4, pad=2): c1 -> cat1[:, 128:160] @ 256x256
    conv_mma<4, 2, 32>(dyn, d1w, d1b, cat1, 128, 32, 255, 255, 32, 160, 8, wscr);
    // 3. pool c1 -> (4,32,128,128)
    {
        int total = 4 * 32 * 128 * 128;
        maxpool_kernel<<<(total + 255) / 256, 256>>>(cat1, p1, 32, 160, 128, 256, 256);
    }
    // 4-5. double conv 2 : c2 -> cat2[:, 256:384] @ 128x128
    conv_mma<3, 1, 64>(p1, w2a, b2a, t2, 0, 32, 128, 128, 128, 128, 7, wscr);
    conv_mma<3, 1, 64>(t2, w2b, b2b, cat2, 256, 128, 128, 128, 128, 384, 7, wscr);
    // 6. pool c2 -> (4,128,64,64)
    {
        int total = 4 * 128 * 64 * 64;
        maxpool_kernel<<<(total + 255) / 256, 256>>>(cat2, p2, 128, 384, 256, 128, 128);
    }
    // 7-8. double conv 3 : c3 -> cat3[:, 512:768] @ 64x64
    conv_mma<3, 1, 64>(p2, w3a, b3a, t3, 0, 128, 64, 64, 256, 256, 6, wscr);
    conv_mma<3, 1, 64>(t3, w3b, b3b, cat3, 512, 256, 64, 64, 256, 768, 6, wscr);
    // 9. pool c3 -> (4,256,32,32)
    {
        int total = 4 * 256 * 32 * 32;
        maxpool_kernel<<<(total + 255) / 256, 256>>>(cat3, p3, 256, 768, 512, 64, 64);
    }
    // 10-11. double conv 4 : (4,512,32,32)
    conv_mma<3, 1, 64>(p3, w4a, b4a, t4, 0, 256, 32, 32, 512, 512, 5, wscr);
    conv_mma<3, 1, 64>(t4, w4b, b4b, h4, 0, 512, 32, 32, 512, 512, 5, wscr);
    // 12. batchnorm stats
    bn_stats_kernel<<<512, 256>>>(h4, g4, be4, bnsc, bnsh);
    // 13. upsample(bn(h4)) -> cat3[:, 0:512] @ 64x64
    {
        long total = (long)4 * 512 * 64 * 64;
        up2_kernel<<<(int)((total + 255) / 256), 256>>>(h4, cat3, 512, 32, 32, 768, bnsc, bnsh);
    }
    // 14-15. double conv u3 : (4,256,64,64)
    conv_mma<3, 1, 64>(cat3, u3a, ub3a, u3t, 0, 768, 64, 64, 256, 256, 6, wscr);
    conv_mma<3, 1, 64>(u3t, u3b, ub3b, u3, 0, 256, 64, 64, 256, 256, 6, wscr);
    // 16. upsample u3 -> cat2[:, 0:256] @ 128x128
    {
        long total = (long)4 * 256 * 128 * 128;
        up2_kernel<<<(int)((total + 255) / 256), 256>>>(u3, cat2, 256, 64, 64, 384, nullptr, nullptr);
    }
    // 17-18. double conv u2 : (4,128,128,128)
    conv_mma<3, 1, 64>(cat2, u2a, ub2a, u2t, 0, 384, 128, 128, 128, 128, 7, wscr);
    conv_mma<3, 1, 64>(u2t, u2b, ub2b, u2, 0, 128, 128, 128, 128, 128, 7, wscr);
    // 19. upsample u2 -> cat1[:, 0:128] @ 256x256
    {
        long total = (long)4 * 128 * 256 * 256;
        up2_kernel<<<(int)((total + 255) / 256), 256>>>(u2, cat1, 128, 128, 128, 160, nullptr, nullptr);
    }
    // 20-21. double conv u1 : (4,32,256,256)
    conv_mma<3, 1, 32>(cat1, u1a, ub1a, u1t, 0, 160, 256, 256, 32, 32, 8, wscr);
    conv_mma<3, 1, 32>(u1t, u1b, ub1b, u1, 0, 32, 256, 256, 32, 32, 8, wscr);
    // 22. final 1x1 conv -> (4,1,256,256)
    {
        int total = 4 * 65536;
        conv1x1_kernel<<<(total + 255) / 256, 256>>>(u1, wl, bl, out);
    }
}

// round 10
// speedup vs baseline: 2.8751x; 1.0631x over previous
#include <cuda_runtime.h>
#include <stdint.h>
#include <math.h>

// ---------------------------------------------------------------------------
// UNet forward (B=4, 256x256): convolutions on tensor cores via portable
// mma.sync m16n8k8 tf32. Graph-capturable; all intermediates in device globals.
// ---------------------------------------------------------------------------

#define B4 4

// ---------------- workspace buffers ----------------
__device__ float g_dyn [4*32*255*255];
__device__ float g_p1  [4*32*128*128];
__device__ float g_t2  [4*128*128*128];
__device__ float g_p2  [4*128*64*64];
__device__ float g_t3  [4*256*64*64];
__device__ float g_p3  [4*256*32*32];
__device__ float g_t4  [4*512*32*32];
__device__ float g_h4  [4*512*32*32];
__device__ float g_cat3[4*768*64*64];    // [0:512)=up(bn(h4)), [512:768)=c3
__device__ float g_u3t [4*256*64*64];
__device__ float g_u3  [4*256*64*64];
__device__ float g_cat2[4*384*128*128];  // [0:256)=up(u3), [256:384)=c2
__device__ float g_u2t [4*128*128*128];
__device__ float g_u2  [4*128*128*128];
__device__ float g_cat1[4*160*256*256];  // [0:128)=up(u2), [128:160)=c1
__device__ float g_u1t [4*32*256*256];
__device__ float g_u1  [4*32*256*256];
__device__ float g_bnscale[512];
__device__ float g_bnshift[512];
__device__ __align__(16) float g_wt[7700000];   // transposed tf32 weight arena

// Exact identity: tanh(softplus(x)) = t(t+2)/(t(t+2)+2), t = e^x.
__device__ __forceinline__ float mishf(float x) {
    if (x > 15.f) return x;
    float t = __expf(x);
    float u = fmaf(t, t, t + t);
    return x * __fdividef(u, u + 2.f);
}

__device__ __forceinline__ uint32_t to_tf32(float f) {
    uint32_t v;
    asm("cvt.rna.tf32.f32 %0, %1;" : "=r"(v) : "f"(f));
    return v;
}

__device__ __forceinline__ void mma_tf32(float& d0, float& d1, float& d2, float& d3,
                                         uint32_t a0, uint32_t a1, uint32_t a2, uint32_t a3,
                                         uint32_t b0, uint32_t b1) {
    asm volatile("mma.sync.aligned.m16n8k8.row.col.f32.tf32.tf32.f32 "
                 "{%0,%1,%2,%3}, {%4,%5,%6,%7}, {%8,%9}, {%0,%1,%2,%3};"
                 : "+f"(d0), "+f"(d1), "+f"(d2), "+f"(d3)
                 : "r"(a0), "r"(a1), "r"(a2), "r"(a3), "r"(b0), "r"(b1));
}

// ---------------------------------------------------------------------------
// Weight transform: w[co][ci][rs] (fp32) -> wt[co][rs][ci] (tf32-rounded fp32)
// ---------------------------------------------------------------------------
__global__ void wtrans_kernel(const float* __restrict__ w, float* __restrict__ o,
                              int Ci, int KK, int total)
{
    int idx = blockIdx.x * blockDim.x + threadIdx.x;
    if (idx >= total) return;
    int cikk = Ci * KK;
    int co = idx / cikk;
    int rem = idx - co * cikk;
    int ci = rem / KK;
    int rs = rem - ci * KK;
    o[(co * KK + rs) * Ci + ci] = __uint_as_float(to_tf32(w[idx]));
}

// ---------------------------------------------------------------------------
// Implicit-GEMM conv on mma.sync tf32.
// Block: BM pixels x BN out-chan, BK=32 K-slice (one (r,s), 32 in-channels),
// 256 threads = 8 warps. Warp tile: 32 x (BN/WN), MMA_M=2.
//   BN=128: warp grid 4x2 (32x64);  BN=64: 4x2 (32x32) for small grids;
//   BN=32 : warp grid 8x1 with BM=256 (32x32).
// Requires Ci%32==0, Co%BN==0, HoWo%BM==0, Ho=Wo=2^logWo.
// ---------------------------------------------------------------------------
template<int K, int PAD, int BM, int BN>
__global__ __launch_bounds__(256)
void conv_mma_kernel(const float* __restrict__ in,
                     const float* __restrict__ wtT,   // [Co][K*K][Ci] tf32
                     const float* __restrict__ bias,
                     float* __restrict__ outAdj,
                     int Ci, int Hi, int Wi,
                     int CoutTot, int logWo, int HoWo)
{
    constexpr int BK = 32;
    constexpr int SA = BM + 8;
    constexpr int SB = BN + 8;
    constexpr int WN = (BN >= 64) ? 2 : 1;     // warps along N
    constexpr int WM = 8 / WN;                 // warps along M
    constexpr int WTM = BM / WM;               // 32
    constexpr int WTN = BN / WN;               // 64 or 32
    constexpr int NI = WTN / 8;                // 8 or 4
    constexpr int MMA_M = WTM / 16;            // 2
    constexpr int AG = (BM * BK) / 256;        // A elems per thread (16 or 32)
    constexpr int NB4 = (BN * BK / 4) / 256;   // float4 B loads per thread

    extern __shared__ float sm[];
    float* As = sm;                            // [2][BK][SA]
    float* Bs = sm + 2 * BK * SA;              // [2][BK][SB]

    const int tid = threadIdx.x;
    const int warpId = tid >> 5;
    const int lane = tid & 31;
    const int warpN = (WN == 2) ? (warpId & 1) : 0;
    const int warpM = (WN == 2) ? (warpId >> 1) : warpId;
    const int row = lane >> 2;                 // 0..7
    const int colk = lane & 3;                 // 0..3

    const int b = blockIdx.z;
    const int pixBase = blockIdx.x * BM;
    const int coBase = blockIdx.y * BN;
    const int Wo = 1 << logWo;

    const int m = tid & (BM - 1);
    const int kb0 = (BM == 128) ? ((tid >> 7) * 16) : 0;
    const int pix = pixBase + m;
    const int oy = pix >> logWo;
    const int ox = pix & (Wo - 1);
    const long HiWi = (long)Hi * Wi;
    const float* inB = in + (long)b * Ci * HiWi;
    const int Ktot = K * K * Ci;
    const int cipt = Ci >> 5;
    const int KT = Ktot >> 5;

    float acc[MMA_M][NI][4];
#pragma unroll
    for (int mi = 0; mi < MMA_M; mi++)
#pragma unroll
        for (int ni = 0; ni < NI; ni++)
#pragma unroll
            for (int i = 0; i < 4; i++) acc[mi][ni][i] = 0.f;

    uint32_t aR[AG];
    float4 bR[NB4];

    auto loadGlobal = [&](int kt) {
        int rs = kt / cipt;
        int cb = (kt - rs * cipt) << 5;
        int r = rs / K, s = rs - r * K;
        int gy = oy + r - PAD;
        int gx = ox + s - PAD;
        bool ok = ((unsigned)gy < (unsigned)Hi) && ((unsigned)gx < (unsigned)Wi);
        const float* rowp = inB + (long)cb * HiWi + (long)gy * Wi + gx;
#pragma unroll
        for (int j = 0; j < AG; j++)
            aR[j] = ok ? to_tf32(__ldg(rowp + (long)(kb0 + j) * HiWi)) : 0u;
#pragma unroll
        for (int it = 0; it < NB4; it++) {
            int idx = tid + it * 256;
            int n = idx % BN;
            int k0 = (idx / BN) * 4;
            bR[it] = *(const float4*)(wtT + (long)(coBase + n) * Ktot + kt * 32 + k0);
        }
    };
    auto storeSmem = [&](int buf) {
        float* Ab = As + buf * BK * SA;
#pragma unroll
        for (int j = 0; j < AG; j++)
            Ab[(kb0 + j) * SA + m] = __uint_as_float(aR[j]);
        float* Bb = Bs + buf * BK * SB;
#pragma unroll
        for (int it = 0; it < NB4; it++) {
            int idx = tid + it * 256;
            int n = idx % BN;
            int k0 = (idx / BN) * 4;
            Bb[(k0 + 0) * SB + n] = bR[it].x;
            Bb[(k0 + 1) * SB + n] = bR[it].y;
            Bb[(k0 + 2) * SB + n] = bR[it].z;
            Bb[(k0 + 3) * SB + n] = bR[it].w;
        }
    };
    auto compute = [&](int buf) {
        const float* Ab = As + buf * BK * SA;
        const float* Bb = Bs + buf * BK * SB;
#pragma unroll
        for (int ks = 0; ks < 4; ks++) {
            const int kb = ks * 8;
            uint32_t af[MMA_M][4];
#pragma unroll
            for (int mi = 0; mi < MMA_M; mi++) {
                int m0 = warpM * WTM + mi * 16 + row;
                af[mi][0] = __float_as_uint(Ab[(kb + colk) * SA + m0]);
                af[mi][1] = __float_as_uint(Ab[(kb + colk) * SA + m0 + 8]);
                af[mi][2] = __float_as_uint(Ab[(kb + colk + 4) * SA + m0]);
                af[mi][3] = __float_as_uint(Ab[(kb + colk + 4) * SA + m0 + 8]);
            }
            uint32_t bf[NI][2];
#pragma unroll
            for (int ni = 0; ni < NI; ni++) {
                int n0 = warpN * WTN + ni * 8 + (lane >> 2);
                bf[ni][0] = __float_as_uint(Bb[(kb + colk) * SB + n0]);
                bf[ni][1] = __float_as_uint(Bb[(kb + colk + 4) * SB + n0]);
            }
#pragma unroll
            for (int mi = 0; mi < MMA_M; mi++)
#pragma unroll
                for (int ni = 0; ni < NI; ni++)
                    mma_tf32(acc[mi][ni][0], acc[mi][ni][1], acc[mi][ni][2], acc[mi][ni][3],
                             af[mi][0], af[mi][1], af[mi][2], af[mi][3],
                             bf[ni][0], bf[ni][1]);
        }
    };

    loadGlobal(0);
    storeSmem(0);
    __syncthreads();

    for (int kt = 0; kt < KT; kt++) {
        const int cur = kt & 1;
        if (kt + 1 < KT) loadGlobal(kt + 1);
        compute(cur);
        if (kt + 1 < KT) storeSmem(cur ^ 1);
        __syncthreads();
    }

#pragma unroll
    for (int mi = 0; mi < MMA_M; mi++) {
#pragma unroll
        for (int ni = 0; ni < NI; ni++) {
            int pixr = pixBase + warpM * WTM + mi * 16 + row;
            int co = coBase + warpN * WTN + ni * 8 + 2 * colk;
            float bi0 = __ldg(bias + co);
            float bi1 = __ldg(bias + co + 1);
            float* o0 = outAdj + ((long)b * CoutTot + co) * HoWo;
            float* o1 = o0 + HoWo;
            o0[pixr]     = mishf(acc[mi][ni][0] + bi0);
            o1[pixr]     = mishf(acc[mi][ni][1] + bi1);
            o0[pixr + 8] = mishf(acc[mi][ni][2] + bi0);
            o1[pixr + 8] = mishf(acc[mi][ni][3] + bi1);
        }
    }
}

// ---------------- dynamic per-sample conv (K=4, pad=1) + mish ----------------
__global__ void dyn_conv_mish_kernel(const float* __restrict__ x,
                                     const float* __restrict__ w,
                                     float* __restrict__ out)
{
    const int Ho = 255, Wo = 255, Hi = 256, Wi = 256;
    int idx = blockIdx.x * blockDim.x + threadIdx.x;
    int total = 4 * 32 * Ho * Wo;
    if (idx >= total) return;
    int ox = idx % Wo;
    int t = idx / Wo;
    int oy = t % Ho; t /= Ho;
    int co = t % 32; int b = t / 32;
    const float* xb = x + b * Hi * Wi;
    const float* wb = w + (b * 32 + co) * 16;
    float acc = 0.f;
#pragma unroll
    for (int ky = 0; ky < 4; ky++) {
        int iy = oy - 1 + ky;
        if (iy < 0 || iy >= Hi) continue;
#pragma unroll
        for (int kx = 0; kx < 4; kx++) {
            int ix = ox - 1 + kx;
            if (ix < 0 || ix >= Wi) continue;
            acc = fmaf(xb[iy * Wi + ix], wb[ky * 4 + kx], acc);
        }
    }
    out[idx] = mishf(acc);
}

// ---------------- 2x2 maxpool (strided-channel input) ----------------
__global__ void maxpool_kernel(const float* __restrict__ in, float* __restrict__ out,
                               int C, int CinTot, int cinOff, int Hi, int Wi)
{
    int Ho = Hi >> 1, Wo = Wi >> 1;
    int idx = blockIdx.x * blockDim.x + threadIdx.x;
    int total = B4 * C * Ho * Wo;
    if (idx >= total) return;
    int ox = idx % Wo;
    int t = idx / Wo;
    int oy = t % Ho; t /= Ho;
    int c = t % C; int b = t / C;
    const float* p = in + ((long)b * CinTot + cinOff + c) * Hi * Wi + (oy * 2) * Wi + ox * 2;
    float v0 = p[0], v1 = p[1], v2 = p[Wi], v3 = p[Wi + 1];
    out[idx] = fmaxf(fmaxf(v0, v1), fmaxf(v2, v3));
}

// ---------------- batchnorm stats ----------------
__global__ void bn_stats_kernel(const float* __restrict__ h,
                                const float* __restrict__ g,
                                const float* __restrict__ be,
                                float* __restrict__ scale,
                                float* __restrict__ shift)
{
    __shared__ float ss[256], ss2[256];
    int c = blockIdx.x;
    int tid = threadIdx.x;
    float s = 0.f, s2 = 0.f;
    for (int b = 0; b < 4; b++) {
        const float* p = h + ((long)b * 512 + c) * 1024;
        for (int i = tid; i < 1024; i += 256) {
            float v = p[i];
            s += v; s2 += v * v;
        }
    }
    ss[tid] = s; ss2[tid] = s2;
    __syncthreads();
    for (int off = 128; off > 0; off >>= 1) {
        if (tid < off) { ss[tid] += ss[tid + off]; ss2[tid] += ss2[tid + off]; }
        __syncthreads();
    }
    if (tid == 0) {
        float mean = ss[0] * (1.f / 4096.f);
        float var = ss2[0] * (1.f / 4096.f) - mean * mean;
        float sc = g[c] * rsqrtf(var + 1e-5f);
        scale[c] = sc;
        shift[c] = be[c] - mean * sc;
    }
}

// ---------------- bilinear x2 upsample (align_corners=True), optional BN ----
__global__ void up2_kernel(const float* __restrict__ in, float* __restrict__ outbase,
                           int C, int H, int W, int Ccat,
                           const float* __restrict__ scale,
                           const float* __restrict__ shift)
{
    int Ho = 2 * H, Wo = 2 * W;
    long idx = (long)blockIdx.x * blockDim.x + threadIdx.x;
    long total = (long)B4 * C * Ho * Wo;
    if (idx >= total) return;
    int ox = idx % Wo;
    long t = idx / Wo;
    int oy = t % Ho; t /= Ho;
    int c = t % C; int b = (int)(t / C);

    float ry = (float)((double)(H - 1) / (double)(Ho - 1));
    float rx = (float)((double)(W - 1) / (double)(Wo - 1));
    float sy = (float)oy * ry;
    float sx = (float)ox * rx;
    int y0 = (int)floorf(sy);
    int x0 = (int)floorf(sx);
    float fy = sy - (float)y0;
    float fx = sx - (float)x0;
    int y1 = min(y0 + 1, H - 1);
    int x1 = min(x0 + 1, W - 1);

    const float* inC = in + ((long)b * C + c) * H * W;
    float a0 = inC[y0 * W + x0] * (1.f - fy) + inC[y1 * W + x0] * fy;
    float a1 = inC[y0 * W + x1] * (1.f - fy) + inC[y1 * W + x1] * fx * 0.f + inC[y1 * W + x1] * fy;
    float v = a0 * (1.f - fx) + a1 * fx;
    if (scale) v = v * scale[c] + shift[c];
    outbase[((long)b * Ccat + c) * Ho * Wo + (long)oy * Wo + ox] = v;
}

// ---------------- final 1x1 conv (32 -> 1) ----------------
__global__ void conv1x1_kernel(const float* __restrict__ in,
                               const float* __restrict__ w,
                               const float* __restrict__ bias,
                               float* __restrict__ out)
{
    int idx = blockIdx.x * blockDim.x + threadIdx.x;
    int total = 4 * 65536;
    if (idx >= total) return;
    int hw = idx & 65535;
    int b = idx >> 16;
    float acc = bias[0];
    const float* p = in + (long)b * 32 * 65536 + hw;
#pragma unroll
    for (int ci = 0; ci < 32; ci++) acc = fmaf(p[(long)ci * 65536], w[ci], acc);
    out[idx] = acc;
}

// ---------------------------------------------------------------------------
// Host side
// ---------------------------------------------------------------------------
static float* sym(const void* symbol) {
    void* p = nullptr;
    cudaGetSymbolAddress(&p, symbol);
    return (float*)p;
}

static void wtrans(const float* w, float* dst, int Co, int Ci, int KK) {
    int tot = Co * Ci * KK;
    wtrans_kernel<<<(tot + 255) / 256, 256>>>(w, dst, Ci, KK, tot);
}

template<int K, int PAD, int BM, int BN>
static void conv_mma(const float* in, const float* wtT, const float* bs,
                     float* out, int coutOff,
                     int Ci, int Hi, int Wi, int Co, int CoutTot, int logWo)
{
    const int HoWo = 1 << (2 * logWo);
    const size_t smem = (2 * 32 * (BM + 8) + 2 * 32 * (BN + 8)) * sizeof(float);
    cudaFuncSetAttribute(conv_mma_kernel<K, PAD, BM, BN>,
                         cudaFuncAttributeMaxDynamicSharedMemorySize, (int)smem);
    dim3 g(HoWo / BM, Co / BN, B4);
    conv_mma_kernel<K, PAD, BM, BN><<<g, 256, smem>>>(in, wtT, bs,
        out + (long)coutOff * HoWo, Ci, Hi, Wi, CoutTot, logWo, HoWo);
}

// weight arena offsets (floats)
#define O_D1  0L
#define O_W2A (O_D1  + 32L*32*16)
#define O_W2B (O_W2A + 128L*32*9)
#define O_W3A (O_W2B + 128L*128*9)
#define O_W3B (O_W3A + 256L*128*9)
#define O_W4A (O_W3B + 256L*256*9)
#define O_W4B (O_W4A + 512L*256*9)
#define O_U3A (O_W4B + 512L*512*9)
#define O_U3B (O_U3A + 256L*768*9)
#define O_U2A (O_U3B + 256L*256*9)
#define O_U2B (O_U2A + 128L*384*9)
#define O_U1A (O_U2B + 128L*128*9)
#define O_U1B (O_U1A + 32L*160*9)

extern "C" void kernel_launch(void* const* d_in, const int* in_sizes, int n_in,
                              void* d_out, int out_size)
{
    const float* x   = (const float*)d_in[0];
    const float* w   = (const float*)d_in[1];
    const float* d1w = (const float*)d_in[2];
    const float* d1b = (const float*)d_in[3];
    const float* w2a = (const float*)d_in[4];
    const float* b2a = (const float*)d_in[5];
    const float* w2b = (const float*)d_in[6];
    const float* b2b = (const float*)d_in[7];
    const float* w3a = (const float*)d_in[8];
    const float* b3a = (const float*)d_in[9];
    const float* w3b = (const float*)d_in[10];
    const float* b3b = (const float*)d_in[11];
    const float* w4a = (const float*)d_in[12];
    const float* b4a = (const float*)d_in[13];
    const float* w4b = (const float*)d_in[14];
    const float* b4b = (const float*)d_in[15];
    const float* g4  = (const float*)d_in[16];
    const float* be4 = (const float*)d_in[17];
    const float* u3a = (const float*)d_in[18];
    const float* ub3a= (const float*)d_in[19];
    const float* u3b = (const float*)d_in[20];
    const float* ub3b= (const float*)d_in[21];
    const float* u2a = (const float*)d_in[22];
    const float* ub2a= (const float*)d_in[23];
    const float* u2b = (const float*)d_in[24];
    const float* ub2b= (const float*)d_in[25];
    const float* u1a = (const float*)d_in[26];
    const float* ub1a= (const float*)d_in[27];
    const float* u1b = (const float*)d_in[28];
    const float* ub1b= (const float*)d_in[29];
    const float* wl  = (const float*)d_in[30];
    const float* bl  = (const float*)d_in[31];
    float* out = (float*)d_out;

    float* dyn  = sym(g_dyn);
    float* p1   = sym(g_p1);
    float* t2   = sym(g_t2);
    float* p2   = sym(g_p2);
    float* t3   = sym(g_t3);
    float* p3   = sym(g_p3);
    float* t4   = sym(g_t4);
    float* h4   = sym(g_h4);
    float* cat3 = sym(g_cat3);
    float* u3t  = sym(g_u3t);
    float* u3   = sym(g_u3);
    float* cat2 = sym(g_cat2);
    float* u2t  = sym(g_u2t);
    float* u2   = sym(g_u2);
    float* cat1 = sym(g_cat1);
    float* u1t  = sym(g_u1t);
    float* u1   = sym(g_u1);
    float* bnsc = sym(g_bnscale);
    float* bnsh = sym(g_bnshift);
    float* wa   = sym(g_wt);

    // 0. all weight transforms up-front (independent of conv results)
    wtrans(d1w, wa + O_D1,  32,  32, 16);
    wtrans(w2a, wa + O_W2A, 128, 32,  9);
    wtrans(w2b, wa + O_W2B, 128, 128, 9);
    wtrans(w3a, wa + O_W3A, 256, 128, 9);
    wtrans(w3b, wa + O_W3B, 256, 256, 9);
    wtrans(w4a, wa + O_W4A, 512, 256, 9);
    wtrans(w4b, wa + O_W4B, 512, 512, 9);
    wtrans(u3a, wa + O_U3A, 256, 768, 9);
    wtrans(u3b, wa + O_U3B, 256, 256, 9);
    wtrans(u2a, wa + O_U2A, 128, 384, 9);
    wtrans(u2b, wa + O_U2B, 128, 128, 9);
    wtrans(u1a, wa + O_U1A, 32,  160, 9);
    wtrans(u1b, wa + O_U1B, 32,  32,  9);

    // 1. dynamic conv + mish : (4,32,255,255)
    {
        int total = 4 * 32 * 255 * 255;
        dyn_conv_mish_kernel<<<(total + 255) / 256, 256>>>(x, w, dyn);
    }
    // 2. d1 conv (K=4, pad=2): c1 -> cat1[:, 128:160] @ 256x256
    conv_mma<4, 2, 256, 32>(dyn, wa + O_D1, d1b, cat1, 128, 32, 255, 255, 32, 160, 8);
    // 3. pool c1 -> (4,32,128,128)
    {
        int total = 4 * 32 * 128 * 128;
        maxpool_kernel<<<(total + 255) / 256, 256>>>(cat1, p1, 32, 160, 128, 256, 256);
    }
    // 4-5. double conv 2 : c2 -> cat2[:, 256:384] @ 128x128
    conv_mma<3, 1, 128, 128>(p1, wa + O_W2A, b2a, t2, 0, 32, 128, 128, 128, 128, 7);
    conv_mma<3, 1, 128, 128>(t2, wa + O_W2B, b2b, cat2, 256, 128, 128, 128, 128, 384, 7);
    // 6. pool c2 -> (4,128,64,64)
    {
        int total = 4 * 128 * 64 * 64;
        maxpool_kernel<<<(total + 255) / 256, 256>>>(cat2, p2, 128, 384, 256, 128, 128);
    }
    // 7-8. double conv 3 : c3 -> cat3[:, 512:768] @ 64x64
    conv_mma<3, 1, 128, 128>(p2, wa + O_W3A, b3a, t3, 0, 128, 64, 64, 256, 256, 6);
    conv_mma<3, 1, 128, 128>(t3, wa + O_W3B, b3b, cat3, 512, 256, 64, 64, 256, 768, 6);
    // 9. pool c3 -> (4,256,32,32)
    {
        int total = 4 * 256 * 32 * 32;
        maxpool_kernel<<<(total + 255) / 256, 256>>>(cat3, p3, 256, 768, 512, 64, 64);
    }
    // 10-11. double conv 4 : (4,512,32,32)  (BN=64 for more blocks)
    conv_mma<3, 1, 128, 64>(p3, wa + O_W4A, b4a, t4, 0, 256, 32, 32, 512, 512, 5);
    conv_mma<3, 1, 128, 64>(t4, wa + O_W4B, b4b, h4, 0, 512, 32, 32, 512, 512, 5);
    // 12. batchnorm stats
    bn_stats_kernel<<<512, 256>>>(h4, g4, be4, bnsc, bnsh);
    // 13. upsample(bn(h4)) -> cat3[:, 0:512] @ 64x64
    {
        long total = (long)4 * 512 * 64 * 64;
        up2_kernel<<<(int)((total + 255) / 256), 256>>>(h4, cat3, 512, 32, 32, 768, bnsc, bnsh);
    }
    // 14-15. double conv u3 : (4,256,64,64)
    conv_mma<3, 1, 128, 128>(cat3, wa + O_U3A, ub3a, u3t, 0, 768, 64, 64, 256, 256, 6);
    conv_mma<3, 1, 128, 128>(u3t, wa + O_U3B, ub3b, u3, 0, 256, 64, 64, 256, 256, 6);
    // 16. upsample u3 -> cat2[:, 0:256] @ 128x128
    {
        long total = (long)4 * 256 * 128 * 128;
        up2_kernel<<<(int)((total + 255) / 256), 256>>>(u3, cat2, 256, 64, 64, 384, nullptr, nullptr);
    }
    // 17-18. double conv u2 : (4,128,128,128)
    conv_mma<3, 1, 128, 128>(cat2, wa + O_U2A, ub2a, u2t, 0, 384, 128, 128, 128, 128, 7);
    conv_mma<3, 1, 128, 128>(u2t, wa + O_U2B, ub2b, u2, 0, 128, 128, 128, 128, 128, 7);
    // 19. upsample u2 -> cat1[:, 0:128] @ 256x256
    {
        long total = (long)4 * 128 * 256 * 256;
        up2_kernel<<<(int)((total + 255) / 256), 256>>>(u2, cat1, 128, 128, 128, 160, nullptr, nullptr);
    }
    // 20-21. double conv u1 : (4,32,256,256)
    conv_mma<3, 1, 256, 32>(cat1, wa + O_U1A, ub1a, u1t, 0, 160, 256, 256, 32, 32, 8);
    conv_mma<3, 1, 256, 32>(u1t, wa + O_U1B, ub1b, u1, 0, 32, 256, 256, 32, 32, 8);
    // 22. final 1x1 conv -> (4,1,256,256)
    {
        int total = 4 * 65536;
        conv1x1_kernel<<<(total + 255) / 256, 256>>>(u1, wl, bl, out);
    }
}

// round 12
// speedup vs baseline: 3.0862x; 1.0734x over previous
#include <cuda_runtime.h>
#include <stdint.h>
#include <math.h>

// ---------------------------------------------------------------------------
// UNet forward (B=4, 256x256): convolutions on tensor cores via portable
// mma.sync m16n8k8 tf32 + ldmatrix operand loads.
// Graph-capturable; all intermediates in device globals.
// ---------------------------------------------------------------------------

#define B4 4

// ---------------- workspace buffers ----------------
__device__ float g_dyn [4*32*255*255];
__device__ float g_p1  [4*32*128*128];
__device__ float g_t2  [4*128*128*128];
__device__ float g_p2  [4*128*64*64];
__device__ float g_t3  [4*256*64*64];
__device__ float g_p3  [4*256*32*32];
__device__ float g_t4  [4*512*32*32];
__device__ float g_h4  [4*512*32*32];
__device__ float g_cat3[4*768*64*64];    // [0:512)=up(bn(h4)), [512:768)=c3
__device__ float g_u3t [4*256*64*64];
__device__ float g_u3  [4*256*64*64];
__device__ float g_cat2[4*384*128*128];  // [0:256)=up(u3), [256:384)=c2
__device__ float g_u2t [4*128*128*128];
__device__ float g_u2  [4*128*128*128];
__device__ float g_cat1[4*160*256*256];  // [0:128)=up(u2), [128:160)=c1
__device__ float g_u1t [4*32*256*256];
__device__ float g_u1  [4*32*256*256];
__device__ float g_bnscale[512];
__device__ float g_bnshift[512];
__device__ __align__(16) float g_wt[7700000];   // transposed tf32 weight arena

// Exact identity: tanh(softplus(x)) = t(t+2)/(t(t+2)+2), t = e^x.
__device__ __forceinline__ float mishf(float x) {
    if (x > 15.f) return x;
    float t = __expf(x);
    float u = fmaf(t, t, t + t);
    return x * __fdividef(u, u + 2.f);
}

__device__ __forceinline__ uint32_t to_tf32(float f) {
    uint32_t v;
    asm("cvt.rna.tf32.f32 %0, %1;" : "=r"(v) : "f"(f));
    return v;
}

__device__ __forceinline__ void mma_tf32(float& d0, float& d1, float& d2, float& d3,
                                         uint32_t a0, uint32_t a1, uint32_t a2, uint32_t a3,
                                         uint32_t b0, uint32_t b1) {
    asm volatile("mma.sync.aligned.m16n8k8.row.col.f32.tf32.tf32.f32 "
                 "{%0,%1,%2,%3}, {%4,%5,%6,%7}, {%8,%9}, {%0,%1,%2,%3};"
                 : "+f"(d0), "+f"(d1), "+f"(d2), "+f"(d3)
                 : "r"(a0), "r"(a1), "r"(a2), "r"(a3), "r"(b0), "r"(b1));
}

__device__ __forceinline__ void ldsm_x4(uint32_t& r0, uint32_t& r1, uint32_t& r2, uint32_t& r3,
                                        uint32_t addr) {
    asm volatile("ldmatrix.sync.aligned.m8n8.x4.shared.b16 {%0,%1,%2,%3}, [%4];"
                 : "=r"(r0), "=r"(r1), "=r"(r2), "=r"(r3) : "r"(addr));
}

__device__ __forceinline__ uint32_t smem_u32(const void* p) {
    uint32_t a;
    asm("{ .reg .u64 t; cvta.to.shared.u64 t, %1; cvt.u32.u64 %0, t; }" : "=r"(a) : "l"(p));
    return a;
}

// ---------------------------------------------------------------------------
// Weight transform: w[co][ci][rs] (fp32) -> wt[co][rs][ci] (tf32-rounded fp32)
// ---------------------------------------------------------------------------
__global__ void wtrans_kernel(const float* __restrict__ w, float* __restrict__ o,
                              int Ci, int KK, int total)
{
    int idx = blockIdx.x * blockDim.x + threadIdx.x;
    if (idx >= total) return;
    int cikk = Ci * KK;
    int co = idx / cikk;
    int rem = idx - co * cikk;
    int ci = rem / KK;
    int rs = rem - ci * KK;
    o[(co * KK + rs) * Ci + ci] = __uint_as_float(to_tf32(w[idx]));
}

// ---------------------------------------------------------------------------
// Implicit-GEMM conv on mma.sync tf32 with ldmatrix operand loads.
// Block: BM pixels x BN out-chan, BK=32 K-slice (one (r,s), 32 in-channels),
// 256 threads = 8 warps. A smem [BM][36] (m-major), B smem [BN][36] (n-major),
// both double buffered; fragments via ldmatrix.x4 (tf32 as b16 pairs).
// Requires Ci%32==0, Co%BN==0, HoWo%BM==0, Ho=Wo=2^logWo.
// ---------------------------------------------------------------------------
template<int K, int PAD, int BM, int BN>
__global__ __launch_bounds__(256)
void conv_mma_kernel(const float* __restrict__ in,
                     const float* __restrict__ wtT,   // [Co][K*K][Ci] tf32
                     const float* __restrict__ bias,
                     float* __restrict__ outAdj,
                     int Ci, int Hi, int Wi,
                     int CoutTot, int logWo, int HoWo)
{
    constexpr int BK = 32;
    constexpr int SR = BK + 4;                 // row stride (floats), conflict-free
    constexpr int ASZ = BM * SR;
    constexpr int BSZ = BN * SR;
    constexpr int WN = (BN >= 64) ? 2 : 1;     // warps along N
    constexpr int WM = 8 / WN;
    constexpr int WTM = BM / WM;               // 32
    constexpr int WTN = BN / WN;               // 64 or 32
    constexpr int NI = WTN / 8;                // 8 or 4
    constexpr int NJ = NI / 2;                 // B ldmatrix.x4 count (pairs)
    constexpr int MMA_M = WTM / 16;            // 2
    constexpr int AG = (BM * BK) / 256;        // A elems per thread (16 or 32)
    constexpr int NB4 = (BN * BK / 4) / 256;

    extern __shared__ float sm[];
    float* As = sm;                            // [2][BM][SR]
    float* Bs = sm + 2 * ASZ;                  // [2][BN][SR]
    const uint32_t aBase = smem_u32(As);
    const uint32_t bBase = smem_u32(Bs);

    const int tid = threadIdx.x;
    const int warpId = tid >> 5;
    const int lane = tid & 31;
    const int warpN = (WN == 2) ? (warpId & 1) : 0;
    const int warpM = (WN == 2) ? (warpId >> 1) : warpId;
    const int row = lane >> 2;                 // 0..7 (epilogue)
    const int colk = lane & 3;

    // ldmatrix per-lane source offsets (bytes, within a buffer)
    uint32_t aOff[MMA_M];
#pragma unroll
    for (int mi = 0; mi < MMA_M; mi++)
        aOff[mi] = ((warpM * WTM + mi * 16 + (lane & 15)) * SR + (lane >> 4) * 4) * 4;
    uint32_t bOff[NJ];
#pragma unroll
    for (int nj = 0; nj < NJ; nj++)
        bOff[nj] = ((warpN * WTN + nj * 16 + (lane & 7) + ((lane >> 4) << 3)) * SR
                    + ((lane >> 3) & 1) * 4) * 4;

    const int b = blockIdx.z;
    const int pixBase = blockIdx.x * BM;
    const int coBase = blockIdx.y * BN;
    const int Wo = 1 << logWo;

    const int m = tid & (BM - 1);
    const int kb0 = (BM == 128) ? ((tid >> 7) * 16) : 0;
    const int pix = pixBase + m;
    const int oy = pix >> logWo;
    const int ox = pix & (Wo - 1);
    const long HiWi = (long)Hi * Wi;
    const float* inB = in + (long)b * Ci * HiWi;
    const int Ktot = K * K * Ci;
    const int cipt = Ci >> 5;
    const int KT = Ktot >> 5;

    float acc[MMA_M][NI][4];
#pragma unroll
    for (int mi = 0; mi < MMA_M; mi++)
#pragma unroll
        for (int ni = 0; ni < NI; ni++)
#pragma unroll
            for (int i = 0; i < 4; i++) acc[mi][ni][i] = 0.f;

    uint32_t aR[AG];
    float4 bR[NB4];

    auto loadGlobal = [&](int kt) {
        int rs = kt / cipt;
        int cb = (kt - rs * cipt) << 5;
        int r = rs / K, s = rs - r * K;
        int gy = oy + r - PAD;
        int gx = ox + s - PAD;
        bool ok = ((unsigned)gy < (unsigned)Hi) && ((unsigned)gx < (unsigned)Wi);
        const float* rowp = inB + (long)cb * HiWi + (long)gy * Wi + gx;
#pragma unroll
        for (int j = 0; j < AG; j++)
            aR[j] = ok ? to_tf32(__ldg(rowp + (long)(kb0 + j) * HiWi)) : 0u;
#pragma unroll
        for (int it = 0; it < NB4; it++) {
            int idx = tid + it * 256;
            int n = idx % BN;
            int k0 = (idx / BN) * 4;
            bR[it] = *(const float4*)(wtT + (long)(coBase + n) * Ktot + kt * 32 + k0);
        }
    };
    auto storeSmem = [&](int buf) {
        float* Ab = As + buf * ASZ + m * SR + kb0;
#pragma unroll
        for (int j4 = 0; j4 < AG / 4; j4++)
            *(float4*)(Ab + j4 * 4) = *(float4*)(aR + j4 * 4);
        float* Bb = Bs + buf * BSZ;
#pragma unroll
        for (int it = 0; it < NB4; it++) {
            int idx = tid + it * 256;
            int n = idx % BN;
            int k0 = (idx / BN) * 4;
            *(float4*)(Bb + n * SR + k0) = bR[it];
        }
    };
    auto compute = [&](int buf) {
        const uint32_t aB = aBase + buf * (ASZ * 4);
        const uint32_t bB = bBase + buf * (BSZ * 4);
#pragma unroll
        for (int ks = 0; ks < 4; ks++) {
            uint32_t af[MMA_M][4];
#pragma unroll
            for (int mi = 0; mi < MMA_M; mi++)
                ldsm_x4(af[mi][0], af[mi][1], af[mi][2], af[mi][3],
                        aB + aOff[mi] + ks * 32);
            uint32_t bf[NI][2];
#pragma unroll
            for (int nj = 0; nj < NJ; nj++) {
                uint32_t r0, r1, r2, r3;
                ldsm_x4(r0, r1, r2, r3, bB + bOff[nj] + ks * 32);
                bf[2 * nj][0] = r0; bf[2 * nj][1] = r1;
                bf[2 * nj + 1][0] = r2; bf[2 * nj + 1][1] = r3;
            }
#pragma unroll
            for (int mi = 0; mi < MMA_M; mi++)
#pragma unroll
                for (int ni = 0; ni < NI; ni++)
                    mma_tf32(acc[mi][ni][0], acc[mi][ni][1], acc[mi][ni][2], acc[mi][ni][3],
                             af[mi][0], af[mi][1], af[mi][2], af[mi][3],
                             bf[ni][0], bf[ni][1]);
        }
    };

    loadGlobal(0);
    storeSmem(0);
    __syncthreads();

    for (int kt = 0; kt < KT; kt++) {
        const int cur = kt & 1;
        if (kt + 1 < KT) loadGlobal(kt + 1);
        compute(cur);
        if (kt + 1 < KT) storeSmem(cur ^ 1);
        __syncthreads();
    }

#pragma unroll
    for (int mi = 0; mi < MMA_M; mi++) {
#pragma unroll
        for (int ni = 0; ni < NI; ni++) {
            int pixr = pixBase + warpM * WTM + mi * 16 + row;
            int co = coBase + warpN * WTN + ni * 8 + 2 * colk;
            float bi0 = __ldg(bias + co);
            float bi1 = __ldg(bias + co + 1);
            float* o0 = outAdj + ((long)b * CoutTot + co) * HoWo;
            float* o1 = o0 + HoWo;
            o0[pixr]     = mishf(acc[mi][ni][0] + bi0);
            o1[pixr]     = mishf(acc[mi][ni][1] + bi1);
            o0[pixr + 8] = mishf(acc[mi][ni][2] + bi0);
            o1[pixr + 8] = mishf(acc[mi][ni][3] + bi1);
        }
    }
}

// ---------------- dynamic per-sample conv (K=4, pad=1) + mish ----------------
__global__ void dyn_conv_mish_kernel(const float* __restrict__ x,
                                     const float* __restrict__ w,
                                     float* __restrict__ out)
{
    const int Ho = 255, Wo = 255, Hi = 256, Wi = 256;
    int idx = blockIdx.x * blockDim.x + threadIdx.x;
    int total = 4 * 32 * Ho * Wo;
    if (idx >= total) return;
    int ox = idx % Wo;
    int t = idx / Wo;
    int oy = t % Ho; t /= Ho;
    int co = t % 32; int b = t / 32;
    const float* xb = x + b * Hi * Wi;
    const float* wb = w + (b * 32 + co) * 16;
    float acc = 0.f;
#pragma unroll
    for (int ky = 0; ky < 4; ky++) {
        int iy = oy - 1 + ky;
        if (iy < 0 || iy >= Hi) continue;
#pragma unroll
        for (int kx = 0; kx < 4; kx++) {
            int ix = ox - 1 + kx;
            if (ix < 0 || ix >= Wi) continue;
            acc = fmaf(xb[iy * Wi + ix], wb[ky * 4 + kx], acc);
        }
    }
    out[idx] = mishf(acc);
}

// ---------------- 2x2 maxpool (strided-channel input) ----------------
__global__ void maxpool_kernel(const float* __restrict__ in, float* __restrict__ out,
                               int C, int CinTot, int cinOff, int Hi, int Wi)
{
    int Ho = Hi >> 1, Wo = Wi >> 1;
    int idx = blockIdx.x * blockDim.x + threadIdx.x;
    int total = B4 * C * Ho * Wo;
    if (idx >= total) return;
    int ox = idx % Wo;
    int t = idx / Wo;
    int oy = t % Ho; t /= Ho;
    int c = t % C; int b = t / C;
    const float* p = in + ((long)b * CinTot + cinOff + c) * Hi * Wi + (oy * 2) * Wi + ox * 2;
    float v0 = p[0], v1 = p[1], v2 = p[Wi], v3 = p[Wi + 1];
    out[idx] = fmaxf(fmaxf(v0, v1), fmaxf(v2, v3));
}

// ---------------- batchnorm stats ----------------
__global__ void bn_stats_kernel(const float* __restrict__ h,
                                const float* __restrict__ g,
                                const float* __restrict__ be,
                                float* __restrict__ scale,
                                float* __restrict__ shift)
{
    __shared__ float ss[256], ss2[256];
    int c = blockIdx.x;
    int tid = threadIdx.x;
    float s = 0.f, s2 = 0.f;
    for (int b = 0; b < 4; b++) {
        const float* p = h + ((long)b * 512 + c) * 1024;
        for (int i = tid; i < 1024; i += 256) {
            float v = p[i];
            s += v; s2 += v * v;
        }
    }
    ss[tid] = s; ss2[tid] = s2;
    __syncthreads();
    for (int off = 128; off > 0; off >>= 1) {
        if (tid < off) { ss[tid] += ss[tid + off]; ss2[tid] += ss2[tid + off]; }
        __syncthreads();
    }
    if (tid == 0) {
        float mean = ss[0] * (1.f / 4096.f);
        float var = ss2[0] * (1.f / 4096.f) - mean * mean;
        float sc = g[c] * rsqrtf(var + 1e-5f);
        scale[c] = sc;
        shift[c] = be[c] - mean * sc;
    }
}

// ---------------- bilinear x2 upsample (align_corners=True), optional BN ----
__global__ void up2_kernel(const float* __restrict__ in, float* __restrict__ outbase,
                           int C, int H, int W, int Ccat,
                           const float* __restrict__ scale,
                           const float* __restrict__ shift)
{
    int Ho = 2 * H, Wo = 2 * W;
    long idx = (long)blockIdx.x * blockDim.x + threadIdx.x;
    long total = (long)B4 * C * Ho * Wo;
    if (idx >= total) return;
    int ox = idx % Wo;
    long t = idx / Wo;
    int oy = t % Ho; t /= Ho;
    int c = t % C; int b = (int)(t / C);

    float ry = (float)((double)(H - 1) / (double)(Ho - 1));
    float rx = (float)((double)(W - 1) / (double)(Wo - 1));
    float sy = (float)oy * ry;
    float sx = (float)ox * rx;
    int y0 = (int)floorf(sy);
    int x0 = (int)floorf(sx);
    float fy = sy - (float)y0;
    float fx = sx - (float)x0;
    int y1 = min(y0 + 1, H - 1);
    int x1 = min(x0 + 1, W - 1);

    const float* inC = in + ((long)b * C + c) * H * W;
    float a0 = inC[y0 * W + x0] * (1.f - fy) + inC[y1 * W + x0] * fy;
    float a1 = inC[y0 * W + x1] * (1.f - fy) + inC[y1 * W + x1] * fy;
    float v = a0 * (1.f - fx) + a1 * fx;
    if (scale) v = v * scale[c] + shift[c];
    outbase[((long)b * Ccat + c) * Ho * Wo + (long)oy * Wo + ox] = v;
}

// ---------------- final 1x1 conv (32 -> 1) ----------------
__global__ void conv1x1_kernel(const float* __restrict__ in,
                               const float* __restrict__ w,
                               const float* __restrict__ bias,
                               float* __restrict__ out)
{
    int idx = blockIdx.x * blockDim.x + threadIdx.x;
    int total = 4 * 65536;
    if (idx >= total) return;
    int hw = idx & 65535;
    int b = idx >> 16;
    float acc = bias[0];
    const float* p = in + (long)b * 32 * 65536 + hw;
#pragma unroll
    for (int ci = 0; ci < 32; ci++) acc = fmaf(p[(long)ci * 65536], w[ci], acc);
    out[idx] = acc;
}

// ---------------------------------------------------------------------------
// Host side
// ---------------------------------------------------------------------------
static float* sym(const void* symbol) {
    void* p = nullptr;
    cudaGetSymbolAddress(&p, symbol);
    return (float*)p;
}

static void wtrans(const float* w, float* dst, int Co, int Ci, int KK) {
    int tot = Co * Ci * KK;
    wtrans_kernel<<<(tot + 255) / 256, 256>>>(w, dst, Ci, KK, tot);
}

template<int K, int PAD, int BM, int BN>
static void conv_mma(const float* in, const float* wtT, const float* bs,
                     float* out, int coutOff,
                     int Ci, int Hi, int Wi, int Co, int CoutTot, int logWo)
{
    const int HoWo = 1 << (2 * logWo);
    const size_t smem = (2 * (size_t)BM * 36 + 2 * (size_t)BN * 36) * sizeof(float);
    cudaFuncSetAttribute(conv_mma_kernel<K, PAD, BM, BN>,
                         cudaFuncAttributeMaxDynamicSharedMemorySize, (int)smem);
    dim3 g(HoWo / BM, Co / BN, B4);
    conv_mma_kernel<K, PAD, BM, BN><<<g, 256, smem>>>(in, wtT, bs,
        out + (long)coutOff * HoWo, Ci, Hi, Wi, CoutTot, logWo, HoWo);
}

// weight arena offsets (floats)
#define O_D1  0L
#define O_W2A (O_D1  + 32L*32*16)
#define O_W2B (O_W2A + 128L*32*9)
#define O_W3A (O_W2B + 128L*128*9)
#define O_W3B (O_W3A + 256L*128*9)
#define O_W4A (O_W3B + 256L*256*9)
#define O_W4B (O_W4A + 512L*256*9)
#define O_U3A (O_W4B + 512L*512*9)
#define O_U3B (O_U3A + 256L*768*9)
#define O_U2A (O_U3B + 256L*256*9)
#define O_U2B (O_U2A + 128L*384*9)
#define O_U1A (O_U2B + 128L*128*9)
#define O_U1B (O_U1A + 32L*160*9)

extern "C" void kernel_launch(void* const* d_in, const int* in_sizes, int n_in,
                              void* d_out, int out_size)
{
    const float* x   = (const float*)d_in[0];
    const float* w   = (const float*)d_in[1];
    const float* d1w = (const float*)d_in[2];
    const float* d1b = (const float*)d_in[3];
    const float* w2a = (const float*)d_in[4];
    const float* b2a = (const float*)d_in[5];
    const float* w2b = (const float*)d_in[6];
    const float* b2b = (const float*)d_in[7];
    const float* w3a = (const float*)d_in[8];
    const float* b3a = (const float*)d_in[9];
    const float* w3b = (const float*)d_in[10];
    const float* b3b = (const float*)d_in[11];
    const float* w4a = (const float*)d_in[12];
    const float* b4a = (const float*)d_in[13];
    const float* w4b = (const float*)d_in[14];
    const float* b4b = (const float*)d_in[15];
    const float* g4  = (const float*)d_in[16];
    const float* be4 = (const float*)d_in[17];
    const float* u3a = (const float*)d_in[18];
    const float* ub3a= (const float*)d_in[19];
    const float* u3b = (const float*)d_in[20];
    const float* ub3b= (const float*)d_in[21];
    const float* u2a = (const float*)d_in[22];
    const float* ub2a= (const float*)d_in[23];
    const float* u2b = (const float*)d_in[24];
    const float* ub2b= (const float*)d_in[25];
    const float* u1a = (const float*)d_in[26];
    const float* ub1a= (const float*)d_in[27];
    const float* u1b = (const float*)d_in[28];
    const float* ub1b= (const float*)d_in[29];
    const float* wl  = (const float*)d_in[30];
    const float* bl  = (const float*)d_in[31];
    float* out = (float*)d_out;

    float* dyn  = sym(g_dyn);
    float* p1   = sym(g_p1);
    float* t2   = sym(g_t2);
    float* p2   = sym(g_p2);
    float* t3   = sym(g_t3);
    float* p3   = sym(g_p3);
    float* t4   = sym(g_t4);
    float* h4   = sym(g_h4);
    float* cat3 = sym(g_cat3);
    float* u3t  = sym(g_u3t);
    float* u3   = sym(g_u3);
    float* cat2 = sym(g_cat2);
    float* u2t  = sym(g_u2t);
    float* u2   = sym(g_u2);
    float* cat1 = sym(g_cat1);
    float* u1t  = sym(g_u1t);
    float* u1   = sym(g_u1);
    float* bnsc = sym(g_bnscale);
    float* bnsh = sym(g_bnshift);
    float* wa   = sym(g_wt);

    // 0. all weight transforms up-front (independent of conv results)
    wtrans(d1w, wa + O_D1,  32,  32, 16);
    wtrans(w2a, wa + O_W2A, 128, 32,  9);
    wtrans(w2b, wa + O_W2B, 128, 128, 9);
    wtrans(w3a, wa + O_W3A, 256, 128, 9);
    wtrans(w3b, wa + O_W3B, 256, 256, 9);
    wtrans(w4a, wa + O_W4A, 512, 256, 9);
    wtrans(w4b, wa + O_W4B, 512, 512, 9);
    wtrans(u3a, wa + O_U3A, 256, 768, 9);
    wtrans(u3b, wa + O_U3B, 256, 256, 9);
    wtrans(u2a, wa + O_U2A, 128, 384, 9);
    wtrans(u2b, wa + O_U2B, 128, 128, 9);
    wtrans(u1a, wa + O_U1A, 32,  160, 9);
    wtrans(u1b, wa + O_U1B, 32,  32,  9);

    // 1. dynamic conv + mish : (4,32,255,255)
    {
        int total = 4 * 32 * 255 * 255;
        dyn_conv_mish_kernel<<<(total + 255) / 256, 256>>>(x, w, dyn);
    }
    // 2. d1 conv (K=4, pad=2): c1 -> cat1[:, 128:160] @ 256x256
    conv_mma<4, 2, 256, 32>(dyn, wa + O_D1, d1b, cat1, 128, 32, 255, 255, 32, 160, 8);
    // 3. pool c1 -> (4,32,128,128)
    {
        int total = 4 * 32 * 128 * 128;
        maxpool_kernel<<<(total + 255) / 256, 256>>>(cat1, p1, 32, 160, 128, 256, 256);
    }
    // 4-5. double conv 2 : c2 -> cat2[:, 256:384] @ 128x128
    conv_mma<3, 1, 128, 128>(p1, wa + O_W2A, b2a, t2, 0, 32, 128, 128, 128, 128, 7);
    conv_mma<3, 1, 128, 128>(t2, wa + O_W2B, b2b, cat2, 256, 128, 128, 128, 128, 384, 7);
    // 6. pool c2 -> (4,128,64,64)
    {
        int total = 4 * 128 * 64 * 64;
        maxpool_kernel<<<(total + 255) / 256, 256>>>(cat2, p2, 128, 384, 256, 128, 128);
    }
    // 7-8. double conv 3 : c3 -> cat3[:, 512:768] @ 64x64
    conv_mma<3, 1, 128, 128>(p2, wa + O_W3A, b3a, t3, 0, 128, 64, 64, 256, 256, 6);
    conv_mma<3, 1, 128, 128>(t3, wa + O_W3B, b3b, cat3, 512, 256, 64, 64, 256, 768, 6);
    // 9. pool c3 -> (4,256,32,32)
    {
        int total = 4 * 256 * 32 * 32;
        maxpool_kernel<<<(total + 255) / 256, 256>>>(cat3, p3, 256, 768, 512, 64, 64);
    }
    // 10-11. double conv 4 : (4,512,32,32)  (BN=64 for more blocks)
    conv_mma<3, 1, 128, 64>(p3, wa + O_W4A, b4a, t4, 0, 256, 32, 32, 512, 512, 5);
    conv_mma<3, 1, 128, 64>(t4, wa + O_W4B, b4b, h4, 0, 512, 32, 32, 512, 512, 5);
    // 12. batchnorm stats
    bn_stats_kernel<<<512, 256>>>(h4, g4, be4, bnsc, bnsh);
    // 13. upsample(bn(h4)) -> cat3[:, 0:512] @ 64x64
    {
        long total = (long)4 * 512 * 64 * 64;
        up2_kernel<<<(int)((total + 255) / 256), 256>>>(h4, cat3, 512, 32, 32, 768, bnsc, bnsh);
    }
    // 14-15. double conv u3 : (4,256,64,64)
    conv_mma<3, 1, 128, 128>(cat3, wa + O_U3A, ub3a, u3t, 0, 768, 64, 64, 256, 256, 6);
    conv_mma<3, 1, 128, 128>(u3t, wa + O_U3B, ub3b, u3, 0, 256, 64, 64, 256, 256, 6);
    // 16. upsample u3 -> cat2[:, 0:256] @ 128x128
    {
        long total = (long)4 * 256 * 128 * 128;
        up2_kernel<<<(int)((total + 255) / 256), 256>>>(u3, cat2, 256, 64, 64, 384, nullptr, nullptr);
    }
    // 17-18. double conv u2 : (4,128,128,128)
    conv_mma<3, 1, 128, 128>(cat2, wa + O_U2A, ub2a, u2t, 0, 384, 128, 128, 128, 128, 7);
    conv_mma<3, 1, 128, 128>(u2t, wa + O_U2B, ub2b, u2, 0, 128, 128, 128, 128, 128, 7);
    // 19. upsample u2 -> cat1[:, 0:128] @ 256x256
    {
        long total = (long)4 * 128 * 256 * 256;
        up2_kernel<<<(int)((total + 255) / 256), 256>>>(u2, cat1, 128, 128, 128, 160, nullptr, nullptr);
    }
    // 20-21. double conv u1 : (4,32,256,256)
    conv_mma<3, 1, 256, 32>(cat1, wa + O_U1A, ub1a, u1t, 0, 160, 256, 256, 32, 32, 8);
    conv_mma<3, 1, 256, 32>(u1t, wa + O_U1B, ub1b, u1, 0, 32, 256, 256, 32, 32, 8);
    // 22. final 1x1 conv -> (4,1,256,256)
    {
        int total = 4 * 65536;
        conv1x1_kernel<<<(total + 255) / 256, 256>>>(u1, wl, bl, out);
    }
}

// round 15
// speedup vs baseline: 3.3675x; 1.0912x over previous
#include <cuda_runtime.h>
#include <stdint.h>
#include <math.h>

// ---------------------------------------------------------------------------
// UNet forward (B=4, 256x256): convolutions on tensor cores via portable
// mma.sync m16n8k8 tf32 + ldmatrix. Activations stored pre-rounded to tf32
// so the conv A-path is a plain load. Graph-capturable; no allocation.
// ---------------------------------------------------------------------------

#define B4 4

// ---------------- workspace buffers ----------------
__device__ float g_dyn [4*32*255*255];
__device__ float g_p1  [4*32*128*128];
__device__ float g_t2  [4*128*128*128];
__device__ float g_p2  [4*128*64*64];
__device__ float g_t3  [4*256*64*64];
__device__ float g_p3  [4*256*32*32];
__device__ float g_t4  [4*512*32*32];
__device__ float g_h4  [4*512*32*32];
__device__ float g_cat3[4*768*64*64];    // [0:512)=up(bn(h4)), [512:768)=c3
__device__ float g_u3t [4*256*64*64];
__device__ float g_u3  [4*256*64*64];
__device__ float g_cat2[4*384*128*128];  // [0:256)=up(u3), [256:384)=c2
__device__ float g_u2t [4*128*128*128];
__device__ float g_u2  [4*128*128*128];
__device__ float g_cat1[4*160*256*256];  // [0:128)=up(u2), [128:160)=c1
__device__ float g_u1t [4*32*256*256];
__device__ float g_u1  [4*32*256*256];
__device__ float g_bnscale[512];
__device__ float g_bnshift[512];
__device__ __align__(16) float g_wt[7700000];   // transposed tf32 weight arena

// Exact identity: tanh(softplus(x)) = t(t+2)/(t(t+2)+2), t = e^x.
__device__ __forceinline__ float mishf(float x) {
    if (x > 15.f) return x;
    float t = __expf(x);
    float u = fmaf(t, t, t + t);
    return x * __fdividef(u, u + 2.f);
}

__device__ __forceinline__ uint32_t to_tf32(float f) {
    uint32_t v;
    asm("cvt.rna.tf32.f32 %0, %1;" : "=r"(v) : "f"(f));
    return v;
}
// mish then round to tf32 (activations are consumed only by tf32 GEMMs)
__device__ __forceinline__ float mish_r(float x) {
    return __uint_as_float(to_tf32(mishf(x)));
}

__device__ __forceinline__ void mma_tf32(float& d0, float& d1, float& d2, float& d3,
                                         uint32_t a0, uint32_t a1, uint32_t a2, uint32_t a3,
                                         uint32_t b0, uint32_t b1) {
    asm volatile("mma.sync.aligned.m16n8k8.row.col.f32.tf32.tf32.f32 "
                 "{%0,%1,%2,%3}, {%4,%5,%6,%7}, {%8,%9}, {%0,%1,%2,%3};"
                 : "+f"(d0), "+f"(d1), "+f"(d2), "+f"(d3)
                 : "r"(a0), "r"(a1), "r"(a2), "r"(a3), "r"(b0), "r"(b1));
}

__device__ __forceinline__ void ldsm_x4(uint32_t& r0, uint32_t& r1, uint32_t& r2, uint32_t& r3,
                                        uint32_t addr) {
    asm volatile("ldmatrix.sync.aligned.m8n8.x4.shared.b16 {%0,%1,%2,%3}, [%4];"
                 : "=r"(r0), "=r"(r1), "=r"(r2), "=r"(r3) : "r"(addr));
}

__device__ __forceinline__ uint32_t smem_u32(const void* p) {
    uint32_t a;
    asm("{ .reg .u64 t; cvta.to.shared.u64 t, %1; cvt.u32.u64 %0, t; }" : "=r"(a) : "l"(p));
    return a;
}

// ---------------------------------------------------------------------------
// Weight transform: w[co][ci][rs] (fp32) -> wt[co][rs][ci] (tf32-rounded fp32)
// ---------------------------------------------------------------------------
__global__ void wtrans_kernel(const float* __restrict__ w, float* __restrict__ o,
                              int Ci, int KK, int total)
{
    int idx = blockIdx.x * blockDim.x + threadIdx.x;
    if (idx >= total) return;
    int cikk = Ci * KK;
    int co = idx / cikk;
    int rem = idx - co * cikk;
    int ci = rem / KK;
    int rs = rem - ci * KK;
    o[(co * KK + rs) * Ci + ci] = __uint_as_float(to_tf32(w[idx]));
}

// ---------------------------------------------------------------------------
// Implicit-GEMM conv on mma.sync tf32 with ldmatrix operand loads.
// Block: BM pixels x BN out-chan, BK=32 K-slice (one (r,s), 32 in-channels),
// 256 threads = 8 warps. A smem [BM][36] (m-major), B smem [BN][36] (n-major),
// double buffered; fragments via ldmatrix.x4 (tf32 as b16 pairs).
// All loop indexing is strength-reduced (no divisions in the main loop).
// Requires Ci%32==0, Co%BN==0, HoWo%BM==0, Ho=Wo=2^logWo.
// ---------------------------------------------------------------------------
template<int K, int PAD, int BM, int BN>
__global__ __launch_bounds__(256)
void conv_mma_kernel(const float* __restrict__ in,    // activations pre-rounded to tf32
                     const float* __restrict__ wtT,   // [Co][K*K][Ci] tf32
                     const float* __restrict__ bias,
                     float* __restrict__ outAdj,
                     int Ci, int Hi, int Wi,
                     int CoutTot, int logWo, int HoWo)
{
    constexpr int BK = 32;
    constexpr int SR = BK + 4;                 // row stride (floats), conflict-free
    constexpr int ASZ = BM * SR;
    constexpr int BSZ = BN * SR;
    constexpr int WN = (BN >= 64) ? 2 : 1;     // warps along N
    constexpr int WM = 8 / WN;
    constexpr int WTM = BM / WM;               // 32
    constexpr int WTN = BN / WN;               // 64 or 32
    constexpr int NI = WTN / 8;                // 8 or 4
    constexpr int NJ = NI / 2;                 // B ldmatrix.x4 count
    constexpr int MMA_M = WTM / 16;            // 2
    constexpr int AG = (BM * BK) / 256;        // A elems per thread (16 or 32)
    constexpr int NB4 = (BN * BK / 4) / 256;

    extern __shared__ float sm[];
    float* As = sm;                            // [2][BM][SR]
    float* Bs = sm + 2 * ASZ;                  // [2][BN][SR]
    const uint32_t aBase = smem_u32(As);
    const uint32_t bBase = smem_u32(Bs);

    const int tid = threadIdx.x;
    const int warpId = tid >> 5;
    const int lane = tid & 31;
    const int warpN = (WN == 2) ? (warpId & 1) : 0;
    const int warpM = (WN == 2) ? (warpId >> 1) : warpId;
    const int row = lane >> 2;                 // epilogue
    const int colk = lane & 3;

    // ldmatrix per-lane source offsets (bytes, within a buffer)
    uint32_t aOff[MMA_M];
#pragma unroll
    for (int mi = 0; mi < MMA_M; mi++)
        aOff[mi] = ((warpM * WTM + mi * 16 + (lane & 15)) * SR + (lane >> 4) * 4) * 4;
    uint32_t bOff[NJ];
#pragma unroll
    for (int nj = 0; nj < NJ; nj++)
        bOff[nj] = ((warpN * WTN + nj * 16 + (lane & 7) + ((lane >> 4) << 3)) * SR
                    + ((lane >> 3) & 1) * 4) * 4;

    const int b = blockIdx.z;
    const int pixBase = blockIdx.x * BM;
    const int coBase = blockIdx.y * BN;
    const int Wo = 1 << logWo;

    const int m = tid & (BM - 1);
    const int kb0 = (BM == 128) ? ((tid >> 7) * 16) : 0;
    const int pix = pixBase + m;
    const int oy = pix >> logWo;
    const int ox = pix & (Wo - 1);
    const long HiWi = (long)Hi * Wi;
    const float* inB = in + (long)b * Ci * HiWi;
    const int Ktot = K * K * Ci;
    const int KT = Ktot >> 5;

    float acc[MMA_M][NI][4];
#pragma unroll
    for (int mi = 0; mi < MMA_M; mi++)
#pragma unroll
        for (int ni = 0; ni < NI; ni++)
#pragma unroll
            for (int i = 0; i < 4; i++) acc[mi][ni][i] = 0.f;

    float aR[AG];
    float4 bR[NB4];

    // ---- incremental load state (no divisions in the loop) ----
    int cB_n = 0;                  // channel base within current (r,s)
    int s_n = 0;                   // s counter 0..K-1
    int gy_n = oy - PAD;
    int gx_n = ox - PAD;
    bool ok_n = ((unsigned)gy_n < (unsigned)Hi) && ((unsigned)gx_n < (unsigned)Wi);
    const float* rowbase = inB + (long)gy_n * Wi + gx_n;
    const float* bPtr[NB4];
#pragma unroll
    for (int it = 0; it < NB4; it++) {
        int idx = tid + it * 256;
        int n = idx % BN;
        int k0 = (idx / BN) * 4;
        bPtr[it] = wtT + (long)(coBase + n) * Ktot + k0;
    }

    auto loadGlobal = [&]() {
        const float* rowp = rowbase + (long)(cB_n + kb0) * HiWi;
#pragma unroll
        for (int j = 0; j < AG; j++) {
            aR[j] = ok_n ? __ldg(rowp) : 0.f;
            rowp += HiWi;
        }
#pragma unroll
        for (int it = 0; it < NB4; it++) {
            bR[it] = *(const float4*)bPtr[it];
            bPtr[it] += BK;
        }
        // advance state
        cB_n += BK;
        if (cB_n == Ci) {
            cB_n = 0;
            gx_n++; s_n++;
            if (s_n == K) { s_n = 0; gx_n -= K; gy_n++; }
            ok_n = ((unsigned)gy_n < (unsigned)Hi) && ((unsigned)gx_n < (unsigned)Wi);
            rowbase = inB + (long)gy_n * Wi + gx_n;
        }
    };
    auto storeSmem = [&](int buf) {
        float* Ab = As + buf * ASZ + m * SR + kb0;
#pragma unroll
        for (int j4 = 0; j4 < AG / 4; j4++)
            *(float4*)(Ab + j4 * 4) = *(float4*)(aR + j4 * 4);
        float* Bb = Bs + buf * BSZ;
#pragma unroll
        for (int it = 0; it < NB4; it++) {
            int idx = tid + it * 256;
            int n = idx % BN;
            int k0 = (idx / BN) * 4;
            *(float4*)(Bb + n * SR + k0) = bR[it];
        }
    };
    auto compute = [&](int buf) {
        const uint32_t aB = aBase + buf * (ASZ * 4);
        const uint32_t bB = bBase + buf * (BSZ * 4);
#pragma unroll
        for (int ks = 0; ks < 4; ks++) {
            uint32_t af[MMA_M][4];
#pragma unroll
            for (int mi = 0; mi < MMA_M; mi++)
                ldsm_x4(af[mi][0], af[mi][1], af[mi][2], af[mi][3],
                        aB + aOff[mi] + ks * 32);
            uint32_t bf[NI][2];
#pragma unroll
            for (int nj = 0; nj < NJ; nj++) {
                uint32_t r0, r1, r2, r3;
                ldsm_x4(r0, r1, r2, r3, bB + bOff[nj] + ks * 32);
                bf[2 * nj][0] = r0; bf[2 * nj][1] = r1;
                bf[2 * nj + 1][0] = r2; bf[2 * nj + 1][1] = r3;
            }
#pragma unroll
            for (int mi = 0; mi < MMA_M; mi++)
#pragma unroll
                for (int ni = 0; ni < NI; ni++)
                    mma_tf32(acc[mi][ni][0], acc[mi][ni][1], acc[mi][ni][2], acc[mi][ni][3],
                             af[mi][0], af[mi][1], af[mi][2], af[mi][3],
                             bf[ni][0], bf[ni][1]);
        }
    };

    loadGlobal();
    storeSmem(0);
    __syncthreads();

    for (int kt = 0; kt < KT; kt++) {
        const int cur = kt & 1;
        if (kt + 1 < KT) loadGlobal();
        compute(cur);
        if (kt + 1 < KT) storeSmem(cur ^ 1);
        __syncthreads();
    }

#pragma unroll
    for (int mi = 0; mi < MMA_M; mi++) {
#pragma unroll
        for (int ni = 0; ni < NI; ni++) {
            int pixr = pixBase + warpM * WTM + mi * 16 + row;
            int co = coBase + warpN * WTN + ni * 8 + 2 * colk;
            float bi0 = __ldg(bias + co);
            float bi1 = __ldg(bias + co + 1);
            float* o0 = outAdj + ((long)b * CoutTot + co) * HoWo;
            float* o1 = o0 + HoWo;
            o0[pixr]     = mish_r(acc[mi][ni][0] + bi0);
            o1[pixr]     = mish_r(acc[mi][ni][1] + bi1);
            o0[pixr + 8] = mish_r(acc[mi][ni][2] + bi0);
            o1[pixr + 8] = mish_r(acc[mi][ni][3] + bi1);
        }
    }
}

// ---------------- dynamic per-sample conv (K=4, pad=1) + mish ----------------
__global__ void dyn_conv_mish_kernel(const float* __restrict__ x,
                                     const float* __restrict__ w,
                                     float* __restrict__ out)
{
    const int Ho = 255, Wo = 255, Hi = 256, Wi = 256;
    int idx = blockIdx.x * blockDim.x + threadIdx.x;
    int total = 4 * 32 * Ho * Wo;
    if (idx >= total) return;
    int ox = idx % Wo;
    int t = idx / Wo;
    int oy = t % Ho; t /= Ho;
    int co = t % 32; int b = t / 32;
    const float* xb = x + b * Hi * Wi;
    const float* wb = w + (b * 32 + co) * 16;
    float acc = 0.f;
#pragma unroll
    for (int ky = 0; ky < 4; ky++) {
        int iy = oy - 1 + ky;
        if (iy < 0 || iy >= Hi) continue;
#pragma unroll
        for (int kx = 0; kx < 4; kx++) {
            int ix = ox - 1 + kx;
            if (ix < 0 || ix >= Wi) continue;
            acc = fmaf(xb[iy * Wi + ix], wb[ky * 4 + kx], acc);
        }
    }
    out[idx] = mish_r(acc);
}

// ---------------- 2x2 maxpool (strided-channel input) ----------------
// input pre-rounded; max of rounded values stays rounded.
__global__ void maxpool_kernel(const float* __restrict__ in, float* __restrict__ out,
                               int C, int CinTot, int cinOff, int Hi, int Wi)
{
    int Ho = Hi >> 1, Wo = Wi >> 1;
    int idx = blockIdx.x * blockDim.x + threadIdx.x;
    int total = B4 * C * Ho * Wo;
    if (idx >= total) return;
    int ox = idx % Wo;
    int t = idx / Wo;
    int oy = t % Ho; t /= Ho;
    int c = t % C; int b = t / C;
    const float* p = in + ((long)b * CinTot + cinOff + c) * Hi * Wi + (oy * 2) * Wi + ox * 2;
    float v0 = p[0], v1 = p[1], v2 = p[Wi], v3 = p[Wi + 1];
    out[idx] = fmaxf(fmaxf(v0, v1), fmaxf(v2, v3));
}

// ---------------- batchnorm stats ----------------
__global__ void bn_stats_kernel(const float* __restrict__ h,
                                const float* __restrict__ g,
                                const float* __restrict__ be,
                                float* __restrict__ scale,
                                float* __restrict__ shift)
{
    __shared__ float ss[256], ss2[256];
    int c = blockIdx.x;
    int tid = threadIdx.x;
    float s = 0.f, s2 = 0.f;
    for (int b = 0; b < 4; b++) {
        const float* p = h + ((long)b * 512 + c) * 1024;
        for (int i = tid; i < 1024; i += 256) {
            float v = p[i];
            s += v; s2 += v * v;
        }
    }
    ss[tid] = s; ss2[tid] = s2;
    __syncthreads();
    for (int off = 128; off > 0; off >>= 1) {
        if (tid < off) { ss[tid] += ss[tid + off]; ss2[tid] += ss2[tid + off]; }
        __syncthreads();
    }
    if (tid == 0) {
        float mean = ss[0] * (1.f / 4096.f);
        float var = ss2[0] * (1.f / 4096.f) - mean * mean;
        float sc = g[c] * rsqrtf(var + 1e-5f);
        scale[c] = sc;
        shift[c] = be[c] - mean * sc;
    }
}

// ---------------- bilinear x2 upsample (align_corners=True), optional BN ----
// output rounded to tf32 (consumed only by tf32 convs)
__global__ void up2_kernel(const float* __restrict__ in, float* __restrict__ outbase,
                           int C, int H, int W, int Ccat,
                           const float* __restrict__ scale,
                           const float* __restrict__ shift)
{
    int Ho = 2 * H, Wo = 2 * W;
    long idx = (long)blockIdx.x * blockDim.x + threadIdx.x;
    long total = (long)B4 * C * Ho * Wo;
    if (idx >= total) return;
    int ox = idx % Wo;
    long t = idx / Wo;
    int oy = t % Ho; t /= Ho;
    int c = t % C; int b = (int)(t / C);

    float ry = (float)((double)(H - 1) / (double)(Ho - 1));
    float rx = (float)((double)(W - 1) / (double)(Wo - 1));
    float sy = (float)oy * ry;
    float sx = (float)ox * rx;
    int y0 = (int)floorf(sy);
    int x0 = (int)floorf(sx);
    float fy = sy - (float)y0;
    float fx = sx - (float)x0;
    int y1 = min(y0 + 1, H - 1);
    int x1 = min(x0 + 1, W - 1);

    const float* inC = in + ((long)b * C + c) * H * W;
    float a0 = inC[y0 * W + x0] * (1.f - fy) + inC[y1 * W + x0] * fy;
    float a1 = inC[y0 * W + x1] * (1.f - fy) + inC[y1 * W + x1] * fy;
    float v = a0 * (1.f - fx) + a1 * fx;
    if (scale) v = v * scale[c] + shift[c];
    outbase[((long)b * Ccat + c) * Ho * Wo + (long)oy * Wo + ox] =
        __uint_as_float(to_tf32(v));
}

// ---------------- final 1x1 conv (32 -> 1) ----------------
__global__ void conv1x1_kernel(const float* __restrict__ in,
                               const float* __restrict__ w,
                               const float* __restrict__ bias,
                               float* __restrict__ out)
{
    int idx = blockIdx.x * blockDim.x + threadIdx.x;
    int total = 4 * 65536;
    if (idx >= total) return;
    int hw = idx & 65535;
    int b = idx >> 16;
    float acc = bias[0];
    const float* p = in + (long)b * 32 * 65536 + hw;
#pragma unroll
    for (int ci = 0; ci < 32; ci++) acc = fmaf(p[(long)ci * 65536], w[ci], acc);
    out[idx] = acc;
}

// ---------------------------------------------------------------------------
// Host side
// ---------------------------------------------------------------------------
static float* sym(const void* symbol) {
    void* p = nullptr;
    cudaGetSymbolAddress(&p, symbol);
    return (float*)p;
}

static void wtrans(const float* w, float* dst, int Co, int Ci, int KK) {
    int tot = Co * Ci * KK;
    wtrans_kernel<<<(tot + 255) / 256, 256>>>(w, dst, Ci, KK, tot);
}

template<int K, int PAD, int BM, int BN>
static void conv_mma(const float* in, const float* wtT, const float* bs,
                     float* out, int coutOff,
                     int Ci, int Hi, int Wi, int Co, int CoutTot, int logWo)
{
    const int HoWo = 1 << (2 * logWo);
    const size_t smem = (2 * (size_t)BM * 36 + 2 * (size_t)BN * 36) * sizeof(float);
    cudaFuncSetAttribute(conv_mma_kernel<K, PAD, BM, BN>,
                         cudaFuncAttributeMaxDynamicSharedMemorySize, (int)smem);
    dim3 g(HoWo / BM, Co / BN, B4);
    conv_mma_kernel<K, PAD, BM, BN><<<g, 256, smem>>>(in, wtT, bs,
        out + (long)coutOff * HoWo, Ci, Hi, Wi, CoutTot, logWo, HoWo);
}

// weight arena offsets (floats)
#define O_D1  0L
#define O_W2A (O_D1  + 32L*32*16)
#define O_W2B (O_W2A + 128L*32*9)
#define O_W3A (O_W2B + 128L*128*9)
#define O_W3B (O_W3A + 256L*128*9)
#define O_W4A (O_W3B + 256L*256*9)
#define O_W4B (O_W4A + 512L*256*9)
#define O_U3A (O_W4B + 512L*512*9)
#define O_U3B (O_U3A + 256L*768*9)
#define O_U2A (O_U3B + 256L*256*9)
#define O_U2B (O_U2A + 128L*384*9)
#define O_U1A (O_U2B + 128L*128*9)
#define O_U1B (O_U1A + 32L*160*9)

extern "C" void kernel_launch(void* const* d_in, const int* in_sizes, int n_in,
                              void* d_out, int out_size)
{
    const float* x   = (const float*)d_in[0];
    const float* w   = (const float*)d_in[1];
    const float* d1w = (const float*)d_in[2];
    const float* d1b = (const float*)d_in[3];
    const float* w2a = (const float*)d_in[4];
    const float* b2a = (const float*)d_in[5];
    const float* w2b = (const float*)d_in[6];
    const float* b2b = (const float*)d_in[7];
    const float* w3a = (const float*)d_in[8];
    const float* b3a = (const float*)d_in[9];
    const float* w3b = (const float*)d_in[10];
    const float* b3b = (const float*)d_in[11];
    const float* w4a = (const float*)d_in[12];
    const float* b4a = (const float*)d_in[13];
    const float* w4b = (const float*)d_in[14];
    const float* b4b = (const float*)d_in[15];
    const float* g4  = (const float*)d_in[16];
    const float* be4 = (const float*)d_in[17];
    const float* u3a = (const float*)d_in[18];
    const float* ub3a= (const float*)d_in[19];
    const float* u3b = (const float*)d_in[20];
    const float* ub3b= (const float*)d_in[21];
    const float* u2a = (const float*)d_in[22];
    const float* ub2a= (const float*)d_in[23];
    const float* u2b = (const float*)d_in[24];
    const float* ub2b= (const float*)d_in[25];
    const float* u1a = (const float*)d_in[26];
    const float* ub1a= (const float*)d_in[27];
    const float* u1b = (const float*)d_in[28];
    const float* ub1b= (const float*)d_in[29];
    const float* wl  = (const float*)d_in[30];
    const float* bl  = (const float*)d_in[31];
    float* out = (float*)d_out;

    float* dyn  = sym(g_dyn);
    float* p1   = sym(g_p1);
    float* t2   = sym(g_t2);
    float* p2   = sym(g_p2);
    float* t3   = sym(g_t3);
    float* p3   = sym(g_p3);
    float* t4   = sym(g_t4);
    float* h4   = sym(g_h4);
    float* cat3 = sym(g_cat3);
    float* u3t  = sym(g_u3t);
    float* u3   = sym(g_u3);
    float* cat2 = sym(g_cat2);
    float* u2t  = sym(g_u2t);
    float* u2   = sym(g_u2);
    float* cat1 = sym(g_cat1);
    float* u1t  = sym(g_u1t);
    float* u1   = sym(g_u1);
    float* bnsc = sym(g_bnscale);
    float* bnsh = sym(g_bnshift);
    float* wa   = sym(g_wt);

    // 0. all weight transforms up-front (independent of conv results)
    wtrans(d1w, wa + O_D1,  32,  32, 16);
    wtrans(w2a, wa + O_W2A, 128, 32,  9);
    wtrans(w2b, wa + O_W2B, 128, 128, 9);
    wtrans(w3a, wa + O_W3A, 256, 128, 9);
    wtrans(w3b, wa + O_W3B, 256, 256, 9);
    wtrans(w4a, wa + O_W4A, 512, 256, 9);
    wtrans(w4b, wa + O_W4B, 512, 512, 9);
    wtrans(u3a, wa + O_U3A, 256, 768, 9);
    wtrans(u3b, wa + O_U3B, 256, 256, 9);
    wtrans(u2a, wa + O_U2A, 128, 384, 9);
    wtrans(u2b, wa + O_U2B, 128, 128, 9);
    wtrans(u1a, wa + O_U1A, 32,  160, 9);
    wtrans(u1b, wa + O_U1B, 32,  32,  9);

    // 1. dynamic conv + mish : (4,32,255,255)
    {
        int total = 4 * 32 * 255 * 255;
        dyn_conv_mish_kernel<<<(total + 255) / 256, 256>>>(x, w, dyn);
    }
    // 2. d1 conv (K=4, pad=2): c1 -> cat1[:, 128:160] @ 256x256
    conv_mma<4, 2, 256, 32>(dyn, wa + O_D1, d1b, cat1, 128, 32, 255, 255, 32, 160, 8);
    // 3. pool c1 -> (4,32,128,128)
    {
        int total = 4 * 32 * 128 * 128;
        maxpool_kernel<<<(total + 255) / 256, 256>>>(cat1, p1, 32, 160, 128, 256, 256);
    }
    // 4-5. double conv 2 : c2 -> cat2[:, 256:384] @ 128x128
    conv_mma<3, 1, 128, 128>(p1, wa + O_W2A, b2a, t2, 0, 32, 128, 128, 128, 128, 7);
    conv_mma<3, 1, 128, 128>(t2, wa + O_W2B, b2b, cat2, 256, 128, 128, 128, 128, 384, 7);
    // 6. pool c2 -> (4,128,64,64)
    {
        int total = 4 * 128 * 64 * 64;
        maxpool_kernel<<<(total + 255) / 256, 256>>>(cat2, p2, 128, 384, 256, 128, 128);
    }
    // 7-8. double conv 3 : c3 -> cat3[:, 512:768] @ 64x64
    conv_mma<3, 1, 128, 128>(p2, wa + O_W3A, b3a, t3, 0, 128, 64, 64, 256, 256, 6);
    conv_mma<3, 1, 128, 128>(t3, wa + O_W3B, b3b, cat3, 512, 256, 64, 64, 256, 768, 6);
    // 9. pool c3 -> (4,256,32,32)
    {
        int total = 4 * 256 * 32 * 32;
        maxpool_kernel<<<(total + 255) / 256, 256>>>(cat3, p3, 256, 768, 512, 64, 64);
    }
    // 10-11. double conv 4 : (4,512,32,32)  (BN=64 for more blocks)
    conv_mma<3, 1, 128, 64>(p3, wa + O_W4A, b4a, t4, 0, 256, 32, 32, 512, 512, 5);
    conv_mma<3, 1, 128, 64>(t4, wa + O_W4B, b4b, h4, 0, 512, 32, 32, 512, 512, 5);
    // 12. batchnorm stats
    bn_stats_kernel<<<512, 256>>>(h4, g4, be4, bnsc, bnsh);
    // 13. upsample(bn(h4)) -> cat3[:, 0:512] @ 64x64
    {
        long total = (long)4 * 512 * 64 * 64;
        up2_kernel<<<(int)((total + 255) / 256), 256>>>(h4, cat3, 512, 32, 32, 768, bnsc, bnsh);
    }
    // 14-15. double conv u3 : (4,256,64,64)
    conv_mma<3, 1, 128, 128>(cat3, wa + O_U3A, ub3a, u3t, 0, 768, 64, 64, 256, 256, 6);
    conv_mma<3, 1, 128, 128>(u3t, wa + O_U3B, ub3b, u3, 0, 256, 64, 64, 256, 256, 6);
    // 16. upsample u3 -> cat2[:, 0:256] @ 128x128
    {
        long total = (long)4 * 256 * 128 * 128;
        up2_kernel<<<(int)((total + 255) / 256), 256>>>(u3, cat2, 256, 64, 64, 384, nullptr, nullptr);
    }
    // 17-18. double conv u2 : (4,128,128,128)
    conv_mma<3, 1, 128, 128>(cat2, wa + O_U2A, ub2a, u2t, 0, 384, 128, 128, 128, 128, 7);
    conv_mma<3, 1, 128, 128>(u2t, wa + O_U2B, ub2b, u2, 0, 128, 128, 128, 128, 128, 7);
    // 19. upsample u2 -> cat1[:, 0:128] @ 256x256
    {
        long total = (long)4 * 128 * 256 * 256;
        up2_kernel<<<(int)((total + 255) / 256), 256>>>(u2, cat1, 128, 128, 128, 160, nullptr, nullptr);
    }
    // 20-21. double conv u1 : (4,32,256,256)
    conv_mma<3, 1, 256, 32>(cat1, wa + O_U1A, ub1a, u1t, 0, 160, 256, 256, 32, 32, 8);
    conv_mma<3, 1, 256, 32>(u1t, wa + O_U1B, ub1b, u1, 0, 32, 256, 256, 32, 32, 8);
    // 22. final 1x1 conv -> (4,1,256,256)
    {
        int total = 4 * 65536;
        conv1x1_kernel<<<(total + 255) / 256, 256>>>(u1, wl, bl, out);
    }
}

// round 16
// speedup vs baseline: 3.5953x; 1.0676x over previous
#include <cuda_runtime.h>
#include <stdint.h>
#include <math.h>

// ---------------------------------------------------------------------------
// UNet forward (B=4, 256x256): convolutions on tensor cores via portable
// mma.sync m16n8k8 tf32 + ldmatrix + cp.async 3-stage pipeline.
// Activations stored pre-rounded to tf32. Graph-capturable; no allocation.
// ---------------------------------------------------------------------------

#define B4 4

// ---------------- workspace buffers ----------------
__device__ float g_dyn [4*32*255*255];
__device__ float g_p1  [4*32*128*128];
__device__ float g_t2  [4*128*128*128];
__device__ float g_p2  [4*128*64*64];
__device__ float g_t3  [4*256*64*64];
__device__ float g_p3  [4*256*32*32];
__device__ float g_t4  [4*512*32*32];
__device__ float g_h4  [4*512*32*32];
__device__ float g_cat3[4*768*64*64];    // [0:512)=up(bn(h4)), [512:768)=c3
__device__ float g_u3t [4*256*64*64];
__device__ float g_u3  [4*256*64*64];
__device__ float g_cat2[4*384*128*128];  // [0:256)=up(u3), [256:384)=c2
__device__ float g_u2t [4*128*128*128];
__device__ float g_u2  [4*128*128*128];
__device__ float g_cat1[4*160*256*256];  // [0:128)=up(u2), [128:160)=c1
__device__ float g_u1t [4*32*256*256];
__device__ float g_u1  [4*32*256*256];
__device__ float g_bnscale[512];
__device__ float g_bnshift[512];
__device__ __align__(16) float g_wt[7700000];   // transposed tf32 weight arena

// Exact identity: tanh(softplus(x)) = t(t+2)/(t(t+2)+2), t = e^x.
__device__ __forceinline__ float mishf(float x) {
    if (x > 15.f) return x;
    float t = __expf(x);
    float u = fmaf(t, t, t + t);
    return x * __fdividef(u, u + 2.f);
}

__device__ __forceinline__ uint32_t to_tf32(float f) {
    uint32_t v;
    asm("cvt.rna.tf32.f32 %0, %1;" : "=r"(v) : "f"(f));
    return v;
}
__device__ __forceinline__ float mish_r(float x) {
    return __uint_as_float(to_tf32(mishf(x)));
}

__device__ __forceinline__ void mma_tf32(float& d0, float& d1, float& d2, float& d3,
                                         uint32_t a0, uint32_t a1, uint32_t a2, uint32_t a3,
                                         uint32_t b0, uint32_t b1) {
    asm volatile("mma.sync.aligned.m16n8k8.row.col.f32.tf32.tf32.f32 "
                 "{%0,%1,%2,%3}, {%4,%5,%6,%7}, {%8,%9}, {%0,%1,%2,%3};"
                 : "+f"(d0), "+f"(d1), "+f"(d2), "+f"(d3)
                 : "r"(a0), "r"(a1), "r"(a2), "r"(a3), "r"(b0), "r"(b1));
}

__device__ __forceinline__ void ldsm_x4(uint32_t& r0, uint32_t& r1, uint32_t& r2, uint32_t& r3,
                                        uint32_t addr) {
    asm volatile("ldmatrix.sync.aligned.m8n8.x4.shared.b16 {%0,%1,%2,%3}, [%4];"
                 : "=r"(r0), "=r"(r1), "=r"(r2), "=r"(r3) : "r"(addr));
}

__device__ __forceinline__ uint32_t smem_u32(const void* p) {
    uint32_t a;
    asm("{ .reg .u64 t; cvta.to.shared.u64 t, %1; cvt.u32.u64 %0, t; }" : "=r"(a) : "l"(p));
    return a;
}

__device__ __forceinline__ void cp_async4(uint32_t dst, const void* src, int src_sz) {
    asm volatile("cp.async.ca.shared.global [%0], [%1], 4, %2;"
                 :: "r"(dst), "l"(src), "r"(src_sz));
}
__device__ __forceinline__ void cp_async16(uint32_t dst, const void* src) {
    asm volatile("cp.async.cg.shared.global [%0], [%1], 16;" :: "r"(dst), "l"(src));
}
__device__ __forceinline__ void cp_commit() {
    asm volatile("cp.async.commit_group;" ::: "memory");
}
template<int N>
__device__ __forceinline__ void cp_wait() {
    asm volatile("cp.async.wait_group %0;" :: "n"(N) : "memory");
}

// ---------------------------------------------------------------------------
// Weight transform: w[co][ci][rs] (fp32) -> wt[co][rs][ci] (tf32-rounded fp32)
// ---------------------------------------------------------------------------
__global__ void wtrans_kernel(const float* __restrict__ w, float* __restrict__ o,
                              int Ci, int KK, int total)
{
    int idx = blockIdx.x * blockDim.x + threadIdx.x;
    if (idx >= total) return;
    int cikk = Ci * KK;
    int co = idx / cikk;
    int rem = idx - co * cikk;
    int ci = rem / KK;
    int rs = rem - ci * KK;
    o[(co * KK + rs) * Ci + ci] = __uint_as_float(to_tf32(w[idx]));
}

// ---------------------------------------------------------------------------
// Implicit-GEMM conv: mma.sync tf32, ldmatrix fragments, cp.async 3-stage
// pipeline. Block: BM pixels x BN out-chan, BK=32 K-slice (one (r,s), 32 in-
// channels), 256 threads = 8 warps. A smem [BM][36], B smem [BN][36].
// Requires Ci%32==0, Co%BN==0, HoWo%BM==0, Ho=Wo=2^logWo.
// ---------------------------------------------------------------------------
template<int K, int PAD, int BM, int BN>
__global__ __launch_bounds__(256)
void conv_mma_kernel(const float* __restrict__ in,    // pre-rounded tf32
                     const float* __restrict__ wtT,   // [Co][K*K][Ci] tf32
                     const float* __restrict__ bias,
                     float* __restrict__ outAdj,
                     int Ci, int Hi, int Wi,
                     int CoutTot, int logWo, int HoWo)
{
    constexpr int BK = 32;
    constexpr int ST = 3;                      // pipeline stages
    constexpr int SR = BK + 4;                 // row stride (floats)
    constexpr int ASZ = BM * SR;
    constexpr int BSZ = BN * SR;
    constexpr int WN = (BN >= 64) ? 2 : 1;
    constexpr int WM = 8 / WN;
    constexpr int WTM = BM / WM;               // 32
    constexpr int WTN = BN / WN;               // 64 or 32
    constexpr int NI = WTN / 8;
    constexpr int NJ = NI / 2;
    constexpr int MMA_M = WTM / 16;            // 2
    constexpr int AG = (BM * BK) / 256;        // A elems/thread (16 or 32)
    constexpr int NB4 = (BN * BK / 4) / 256;

    extern __shared__ float sm[];
    float* As = sm;                            // [ST][BM][SR]
    float* Bs = sm + ST * ASZ;                 // [ST][BN][SR]
    const uint32_t aBase = smem_u32(As);
    const uint32_t bBase = smem_u32(Bs);

    const int tid = threadIdx.x;
    const int warpId = tid >> 5;
    const int lane = tid & 31;
    const int warpN = (WN == 2) ? (warpId & 1) : 0;
    const int warpM = (WN == 2) ? (warpId >> 1) : warpId;
    const int row = lane >> 2;
    const int colk = lane & 3;

    uint32_t aOff[MMA_M];
#pragma unroll
    for (int mi = 0; mi < MMA_M; mi++)
        aOff[mi] = ((warpM * WTM + mi * 16 + (lane & 15)) * SR + (lane >> 4) * 4) * 4;
    uint32_t bOff[NJ];
#pragma unroll
    for (int nj = 0; nj < NJ; nj++)
        bOff[nj] = ((warpN * WTN + nj * 16 + (lane & 7) + ((lane >> 4) << 3)) * SR
                    + ((lane >> 3) & 1) * 4) * 4;

    const int b = blockIdx.z;
    const int pixBase = blockIdx.x * BM;
    const int coBase = blockIdx.y * BN;
    const int Wo = 1 << logWo;

    const int m = tid & (BM - 1);
    const int kb0 = (BM == 128) ? ((tid >> 7) * 16) : 0;
    const int pix = pixBase + m;
    const int oy = pix >> logWo;
    const int ox = pix & (Wo - 1);
    const long HiWi = (long)Hi * Wi;
    const float* inB = in + (long)b * Ci * HiWi;
    const int Ktot = K * K * Ci;
    const int KT = Ktot >> 5;

    float acc[MMA_M][NI][4];
#pragma unroll
    for (int mi = 0; mi < MMA_M; mi++)
#pragma unroll
        for (int ni = 0; ni < NI; ni++)
#pragma unroll
            for (int i = 0; i < 4; i++) acc[mi][ni][i] = 0.f;

    // ---- incremental load state ----
    int cB_n = 0;
    int s_n = 0;
    int gy_n = oy - PAD;
    int gx_n = ox - PAD;
    bool ok_n = ((unsigned)gy_n < (unsigned)Hi) && ((unsigned)gx_n < (unsigned)Wi);
    const float* rowbase = inB + (long)gy_n * Wi + gx_n;
    const float* bPtr[NB4];
    uint32_t bDstOff[NB4];
#pragma unroll
    for (int it = 0; it < NB4; it++) {
        int idx = tid + it * 256;
        int n = idx % BN;
        int k0 = (idx / BN) * 4;
        bPtr[it] = wtT + (long)(coBase + n) * Ktot + k0;
        bDstOff[it] = (n * SR + k0) * 4;
    }
    const uint32_t aDstOff = (m * SR + kb0) * 4;

    auto issueLoads = [&](int stage) {
        const float* rowp = rowbase + (long)(cB_n + kb0) * HiWi;
        const uint32_t aDst = aBase + stage * (ASZ * 4) + aDstOff;
        const int sz = ok_n ? 4 : 0;
#pragma unroll
        for (int j = 0; j < AG; j++) {
            cp_async4(aDst + j * 4, rowp, sz);
            rowp += HiWi;
        }
        const uint32_t bDst = bBase + stage * (BSZ * 4);
#pragma unroll
        for (int it = 0; it < NB4; it++) {
            cp_async16(bDst + bDstOff[it], bPtr[it]);
            bPtr[it] += BK;
        }
        // advance state
        cB_n += BK;
        if (cB_n == Ci) {
            cB_n = 0;
            gx_n++; s_n++;
            if (s_n == K) { s_n = 0; gx_n -= K; gy_n++; }
            ok_n = ((unsigned)gy_n < (unsigned)Hi) && ((unsigned)gx_n < (unsigned)Wi);
            rowbase = inB + (long)gy_n * Wi + gx_n;
        }
    };
    auto compute = [&](int stage) {
        const uint32_t aB = aBase + stage * (ASZ * 4);
        const uint32_t bB = bBase + stage * (BSZ * 4);
#pragma unroll
        for (int ks = 0; ks < 4; ks++) {
            uint32_t af[MMA_M][4];
#pragma unroll
            for (int mi = 0; mi < MMA_M; mi++)
                ldsm_x4(af[mi][0], af[mi][1], af[mi][2], af[mi][3],
                        aB + aOff[mi] + ks * 32);
            uint32_t bf[NI][2];
#pragma unroll
            for (int nj = 0; nj < NJ; nj++) {
                uint32_t r0, r1, r2, r3;
                ldsm_x4(r0, r1, r2, r3, bB + bOff[nj] + ks * 32);
                bf[2 * nj][0] = r0; bf[2 * nj][1] = r1;
                bf[2 * nj + 1][0] = r2; bf[2 * nj + 1][1] = r3;
            }
#pragma unroll
            for (int mi = 0; mi < MMA_M; mi++)
#pragma unroll
                for (int ni = 0; ni < NI; ni++)
                    mma_tf32(acc[mi][ni][0], acc[mi][ni][1], acc[mi][ni][2], acc[mi][ni][3],
                             af[mi][0], af[mi][1], af[mi][2], af[mi][3],
                             bf[ni][0], bf[ni][1]);
        }
    };

    // ---- prologue: stages 0..ST-2 in flight ----
#pragma unroll
    for (int s = 0; s < ST - 1; s++) {
        if (s < KT) issueLoads(s);
        cp_commit();
    }

    int stage = 0;
    for (int kt = 0; kt < KT; kt++) {
        cp_wait<ST - 2>();          // tile kt's copies done (this thread)
        __syncthreads();            // visible block-wide; all warps past compute(kt-1)
        if (kt + ST - 1 < KT) issueLoads((stage + ST - 1 >= ST) ? stage - 1 : stage + ST - 1);
        cp_commit();
        compute(stage);
        stage = (stage + 1 == ST) ? 0 : stage + 1;
    }

#pragma unroll
    for (int mi = 0; mi < MMA_M; mi++) {
#pragma unroll
        for (int ni = 0; ni < NI; ni++) {
            int pixr = pixBase + warpM * WTM + mi * 16 + row;
            int co = coBase + warpN * WTN + ni * 8 + 2 * colk;
            float bi0 = __ldg(bias + co);
            float bi1 = __ldg(bias + co + 1);
            float* o0 = outAdj + ((long)b * CoutTot + co) * HoWo;
            float* o1 = o0 + HoWo;
            o0[pixr]     = mish_r(acc[mi][ni][0] + bi0);
            o1[pixr]     = mish_r(acc[mi][ni][1] + bi1);
            o0[pixr + 8] = mish_r(acc[mi][ni][2] + bi0);
            o1[pixr + 8] = mish_r(acc[mi][ni][3] + bi1);
        }
    }
}

// ---------------- dynamic per-sample conv (K=4, pad=1) + mish ----------------
__global__ void dyn_conv_mish_kernel(const float* __restrict__ x,
                                     const float* __restrict__ w,
                                     float* __restrict__ out)
{
    const int Ho = 255, Wo = 255, Hi = 256, Wi = 256;
    int idx = blockIdx.x * blockDim.x + threadIdx.x;
    int total = 4 * 32 * Ho * Wo;
    if (idx >= total) return;
    int ox = idx % Wo;
    int t = idx / Wo;
    int oy = t % Ho; t /= Ho;
    int co = t % 32; int b = t / 32;
    const float* xb = x + b * Hi * Wi;
    const float* wb = w + (b * 32 + co) * 16;
    float acc = 0.f;
#pragma unroll
    for (int ky = 0; ky < 4; ky++) {
        int iy = oy - 1 + ky;
        if (iy < 0 || iy >= Hi) continue;
#pragma unroll
        for (int kx = 0; kx < 4; kx++) {
            int ix = ox - 1 + kx;
            if (ix < 0 || ix >= Wi) continue;
            acc = fmaf(xb[iy * Wi + ix], wb[ky * 4 + kx], acc);
        }
    }
    out[idx] = mish_r(acc);
}

// ---------------- 2x2 maxpool (strided-channel input) ----------------
__global__ void maxpool_kernel(const float* __restrict__ in, float* __restrict__ out,
                               int C, int CinTot, int cinOff, int Hi, int Wi)
{
    int Ho = Hi >> 1, Wo = Wi >> 1;
    int idx = blockIdx.x * blockDim.x + threadIdx.x;
    int total = B4 * C * Ho * Wo;
    if (idx >= total) return;
    int ox = idx % Wo;
    int t = idx / Wo;
    int oy = t % Ho; t /= Ho;
    int c = t % C; int b = t / C;
    const float* p = in + ((long)b * CinTot + cinOff + c) * Hi * Wi + (oy * 2) * Wi + ox * 2;
    float v0 = p[0], v1 = p[1], v2 = p[Wi], v3 = p[Wi + 1];
    out[idx] = fmaxf(fmaxf(v0, v1), fmaxf(v2, v3));
}

// ---------------- batchnorm stats ----------------
__global__ void bn_stats_kernel(const float* __restrict__ h,
                                const float* __restrict__ g,
                                const float* __restrict__ be,
                                float* __restrict__ scale,
                                float* __restrict__ shift)
{
    __shared__ float ss[256], ss2[256];
    int c = blockIdx.x;
    int tid = threadIdx.x;
    float s = 0.f, s2 = 0.f;
    for (int b = 0; b < 4; b++) {
        const float* p = h + ((long)b * 512 + c) * 1024;
        for (int i = tid; i < 1024; i += 256) {
            float v = p[i];
            s += v; s2 += v * v;
        }
    }
    ss[tid] = s; ss2[tid] = s2;
    __syncthreads();
    for (int off = 128; off > 0; off >>= 1) {
        if (tid < off) { ss[tid] += ss[tid + off]; ss2[tid] += ss2[tid + off]; }
        __syncthreads();
    }
    if (tid == 0) {
        float mean = ss[0] * (1.f / 4096.f);
        float var = ss2[0] * (1.f / 4096.f) - mean * mean;
        float sc = g[c] * rsqrtf(var + 1e-5f);
        scale[c] = sc;
        shift[c] = be[c] - mean * sc;
    }
}

// ---------------- bilinear x2 upsample (align_corners=True), optional BN ----
__global__ void up2_kernel(const float* __restrict__ in, float* __restrict__ outbase,
                           int C, int H, int W, int Ccat,
                           const float* __restrict__ scale,
                           const float* __restrict__ shift)
{
    int Ho = 2 * H, Wo = 2 * W;
    long idx = (long)blockIdx.x * blockDim.x + threadIdx.x;
    long total = (long)B4 * C * Ho * Wo;
    if (idx >= total) return;
    int ox = idx % Wo;
    long t = idx / Wo;
    int oy = t % Ho; t /= Ho;
    int c = t % C; int b = (int)(t / C);

    float ry = (float)((double)(H - 1) / (double)(Ho - 1));
    float rx = (float)((double)(W - 1) / (double)(Wo - 1));
    float sy = (float)oy * ry;
    float sx = (float)ox * rx;
    int y0 = (int)floorf(sy);
    int x0 = (int)floorf(sx);
    float fy = sy - (float)y0;
    float fx = sx - (float)x0;
    int y1 = min(y0 + 1, H - 1);
    int x1 = min(x0 + 1, W - 1);

    const float* inC = in + ((long)b * C + c) * H * W;
    float a0 = inC[y0 * W + x0] * (1.f - fy) + inC[y1 * W + x0] * fy;
    float a1 = inC[y0 * W + x1] * (1.f - fy) + inC[y1 * W + x1] * fy;
    float v = a0 * (1.f - fx) + a1 * fx;
    if (scale) v = v * scale[c] + shift[c];
    outbase[((long)b * Ccat + c) * Ho * Wo + (long)oy * Wo + ox] =
        __uint_as_float(to_tf32(v));
}

// ---------------- final 1x1 conv (32 -> 1) ----------------
__global__ void conv1x1_kernel(const float* __restrict__ in,
                               const float* __restrict__ w,
                               const float* __restrict__ bias,
                               float* __restrict__ out)
{
    int idx = blockIdx.x * blockDim.x + threadIdx.x;
    int total = 4 * 65536;
    if (idx >= total) return;
    int hw = idx & 65535;
    int b = idx >> 16;
    float acc = bias[0];
    const float* p = in + (long)b * 32 * 65536 + hw;
#pragma unroll
    for (int ci = 0; ci < 32; ci++) acc = fmaf(p[(long)ci * 65536], w[ci], acc);
    out[idx] = acc;
}

// ---------------------------------------------------------------------------
// Host side
// ---------------------------------------------------------------------------
static float* sym(const void* symbol) {
    void* p = nullptr;
    cudaGetSymbolAddress(&p, symbol);
    return (float*)p;
}

static void wtrans(const float* w, float* dst, int Co, int Ci, int KK) {
    int tot = Co * Ci * KK;
    wtrans_kernel<<<(tot + 255) / 256, 256>>>(w, dst, Ci, KK, tot);
}

template<int K, int PAD, int BM, int BN>
static void conv_mma(const float* in, const float* wtT, const float* bs,
                     float* out, int coutOff,
                     int Ci, int Hi, int Wi, int Co, int CoutTot, int logWo)
{
    const int HoWo = 1 << (2 * logWo);
    const size_t smem = (3 * (size_t)BM * 36 + 3 * (size_t)BN * 36) * sizeof(float);
    cudaFuncSetAttribute(conv_mma_kernel<K, PAD, BM, BN>,
                         cudaFuncAttributeMaxDynamicSharedMemorySize, (int)smem);
    dim3 g(HoWo / BM, Co / BN, B4);
    conv_mma_kernel<K, PAD, BM, BN><<<g, 256, smem>>>(in, wtT, bs,
        out + (long)coutOff * HoWo, Ci, Hi, Wi, CoutTot, logWo, HoWo);
}

// weight arena offsets (floats)
#define O_D1  0L
#define O_W2A (O_D1  + 32L*32*16)
#define O_W2B (O_W2A + 128L*32*9)
#define O_W3A (O_W2B + 128L*128*9)
#define O_W3B (O_W3A + 256L*128*9)
#define O_W4A (O_W3B + 256L*256*9)
#define O_W4B (O_W4A + 512L*256*9)
#define O_U3A (O_W4B + 512L*512*9)
#define O_U3B (O_U3A + 256L*768*9)
#define O_U2A (O_U3B + 256L*256*9)
#define O_U2B (O_U2A + 128L*384*9)
#define O_U1A (O_U2B + 128L*128*9)
#define O_U1B (O_U1A + 32L*160*9)

extern "C" void kernel_launch(void* const* d_in, const int* in_sizes, int n_in,
                              void* d_out, int out_size)
{
    const float* x   = (const float*)d_in[0];
    const float* w   = (const float*)d_in[1];
    const float* d1w = (const float*)d_in[2];
    const float* d1b = (const float*)d_in[3];
    const float* w2a = (const float*)d_in[4];
    const float* b2a = (const float*)d_in[5];
    const float* w2b = (const float*)d_in[6];
    const float* b2b = (const float*)d_in[7];
    const float* w3a = (const float*)d_in[8];
    const float* b3a = (const float*)d_in[9];
    const float* w3b = (const float*)d_in[10];
    const float* b3b = (const float*)d_in[11];
    const float* w4a = (const float*)d_in[12];
    const float* b4a = (const float*)d_in[13];
    const float* w4b = (const float*)d_in[14];
    const float* b4b = (const float*)d_in[15];
    const float* g4  = (const float*)d_in[16];
    const float* be4 = (const float*)d_in[17];
    const float* u3a = (const float*)d_in[18];
    const float* ub3a= (const float*)d_in[19];
    const float* u3b = (const float*)d_in[20];
    const float* ub3b= (const float*)d_in[21];
    const float* u2a = (const float*)d_in[22];
    const float* ub2a= (const float*)d_in[23];
    const float* u2b = (const float*)d_in[24];
    const float* ub2b= (const float*)d_in[25];
    const float* u1a = (const float*)d_in[26];
    const float* ub1a= (const float*)d_in[27];
    const float* u1b = (const float*)d_in[28];
    const float* ub1b= (const float*)d_in[29];
    const float* wl  = (const float*)d_in[30];
    const float* bl  = (const float*)d_in[31];
    float* out = (float*)d_out;

    float* dyn  = sym(g_dyn);
    float* p1   = sym(g_p1);
    float* t2   = sym(g_t2);
    float* p2   = sym(g_p2);
    float* t3   = sym(g_t3);
    float* p3   = sym(g_p3);
    float* t4   = sym(g_t4);
    float* h4   = sym(g_h4);
    float* cat3 = sym(g_cat3);
    float* u3t  = sym(g_u3t);
    float* u3   = sym(g_u3);
    float* cat2 = sym(g_cat2);
    float* u2t  = sym(g_u2t);
    float* u2   = sym(g_u2);
    float* cat1 = sym(g_cat1);
    float* u1t  = sym(g_u1t);
    float* u1   = sym(g_u1);
    float* bnsc = sym(g_bnscale);
    float* bnsh = sym(g_bnshift);
    float* wa   = sym(g_wt);

    // 0. all weight transforms up-front
    wtrans(d1w, wa + O_D1,  32,  32, 16);
    wtrans(w2a, wa + O_W2A, 128, 32,  9);
    wtrans(w2b, wa + O_W2B, 128, 128, 9);
    wtrans(w3a, wa + O_W3A, 256, 128, 9);
    wtrans(w3b, wa + O_W3B, 256, 256, 9);
    wtrans(w4a, wa + O_W4A, 512, 256, 9);
    wtrans(w4b, wa + O_W4B, 512, 512, 9);
    wtrans(u3a, wa + O_U3A, 256, 768, 9);
    wtrans(u3b, wa + O_U3B, 256, 256, 9);
    wtrans(u2a, wa + O_U2A, 128, 384, 9);
    wtrans(u2b, wa + O_U2B, 128, 128, 9);
    wtrans(u1a, wa + O_U1A, 32,  160, 9);
    wtrans(u1b, wa + O_U1B, 32,  32,  9);

    // 1. dynamic conv + mish : (4,32,255,255)
    {
        int total = 4 * 32 * 255 * 255;
        dyn_conv_mish_kernel<<<(total + 255) / 256, 256>>>(x, w, dyn);
    }
    // 2. d1 conv (K=4, pad=2): c1 -> cat1[:, 128:160] @ 256x256
    conv_mma<4, 2, 256, 32>(dyn, wa + O_D1, d1b, cat1, 128, 32, 255, 255, 32, 160, 8);
    // 3. pool c1 -> (4,32,128,128)
    {
        int total = 4 * 32 * 128 * 128;
        maxpool_kernel<<<(total + 255) / 256, 256>>>(cat1, p1, 32, 160, 128, 256, 256);
    }
    // 4-5. double conv 2 : c2 -> cat2[:, 256:384] @ 128x128
    conv_mma<3, 1, 128, 128>(p1, wa + O_W2A, b2a, t2, 0, 32, 128, 128, 128, 128, 7);
    conv_mma<3, 1, 128, 128>(t2, wa + O_W2B, b2b, cat2, 256, 128, 128, 128, 128, 384, 7);
    // 6. pool c2 -> (4,128,64,64)
    {
        int total = 4 * 128 * 64 * 64;
        maxpool_kernel<<<(total + 255) / 256, 256>>>(cat2, p2, 128, 384, 256, 128, 128);
    }
    // 7-8. double conv 3 : c3 -> cat3[:, 512:768] @ 64x64
    conv_mma<3, 1, 128, 128>(p2, wa + O_W3A, b3a, t3, 0, 128, 64, 64, 256, 256, 6);
    conv_mma<3, 1, 128, 128>(t3, wa + O_W3B, b3b, cat3, 512, 256, 64, 64, 256, 768, 6);
    // 9. pool c3 -> (4,256,32,32)
    {
        int total = 4 * 256 * 32 * 32;
        maxpool_kernel<<<(total + 255) / 256, 256>>>(cat3, p3, 256, 768, 512, 64, 64);
    }
    // 10-11. double conv 4 : (4,512,32,32)
    conv_mma<3, 1, 128, 64>(p3, wa + O_W4A, b4a, t4, 0, 256, 32, 32, 512, 512, 5);
    conv_mma<3, 1, 128, 64>(t4, wa + O_W4B, b4b, h4, 0, 512, 32, 32, 512, 512, 5);
    // 12. batchnorm stats
    bn_stats_kernel<<<512, 256>>>(h4, g4, be4, bnsc, bnsh);
    // 13. upsample(bn(h4)) -> cat3[:, 0:512] @ 64x64
    {
        long total = (long)4 * 512 * 64 * 64;
        up2_kernel<<<(int)((total + 255) / 256), 256>>>(h4, cat3, 512, 32, 32, 768, bnsc, bnsh);
    }
    // 14-15. double conv u3 : (4,256,64,64)
    conv_mma<3, 1, 128, 128>(cat3, wa + O_U3A, ub3a, u3t, 0, 768, 64, 64, 256, 256, 6);
    conv_mma<3, 1, 128, 128>(u3t, wa + O_U3B, ub3b, u3, 0, 256, 64, 64, 256, 256, 6);
    // 16. upsample u3 -> cat2[:, 0:256] @ 128x128
    {
        long total = (long)4 * 256 * 128 * 128;
        up2_kernel<<<(int)((total + 255) / 256), 256>>>(u3, cat2, 256, 64, 64, 384, nullptr, nullptr);
    }
    // 17-18. double conv u2 : (4,128,128,128)
    conv_mma<3, 1, 128, 128>(cat2, wa + O_U2A, ub2a, u2t, 0, 384, 128, 128, 128, 128, 7);
    conv_mma<3, 1, 128, 128>(u2t, wa + O_U2B, ub2b, u2, 0, 128, 128, 128, 128, 128, 7);
    // 19. upsample u2 -> cat1[:, 0:128] @ 256x256
    {
        long total = (long)4 * 128 * 256 * 256;
        up2_kernel<<<(int)((total + 255) / 256), 256>>>(u2, cat1, 128, 128, 128, 160, nullptr, nullptr);
    }
    // 20-21. double conv u1 : (4,32,256,256)
    conv_mma<3, 1, 256, 32>(cat1, wa + O_U1A, ub1a, u1t, 0, 160, 256, 256, 32, 32, 8);
    conv_mma<3, 1, 256, 32>(u1t, wa + O_U1B, ub1b, u1, 0, 32, 256, 256, 32, 32, 8);
    // 22. final 1x1 conv -> (4,1,256,256)
    {
        int total = 4 * 65536;
        conv1x1_kernel<<<(total + 255) / 256, 256>>>(u1, wl, bl, out);
    }
}